// round 8
// baseline (speedup 1.0000x reference)
#include <cuda_runtime.h>
#include <math.h>
#include <stdint.h>

#define NB 4
#define NS 2048
#define ND 1024
#define NH 16
#define HDIM 64
#define NM (NB*NS)   // 8192 rows
#define MM (ND*ND)

// Scratch (allocation-free rule: __device__ globals). ~182 MB total.
// g_Q: [bh][s][d]            (natural fp32)
// g_K: [bh][d][key]          key permuted per 64-block: pos=(k&7)*8+((k>>3)&7); tf32
// g_V: [bh][key][d']         d' = (d&7)*8 + (d>>3); tf32
// g_AO: attention out [B,S,D], tf32, K'-interleaved per 32-col block
// g_XP: tf32 x, K'-interleaved;  g_WP: tf32 Wq,Wk,Wv,Wo, K'-interleaved
// K'-interleave within each 32-float block: k = 8s + t + 4e  ->  k' = t*8 + 2s + e
__device__ __align__(256) float g_Q[(size_t)NB*NH*NS*HDIM];
__device__ __align__(256) float g_K[(size_t)NB*NH*NS*HDIM];
__device__ __align__(256) float g_V[(size_t)NB*NH*NS*HDIM];
__device__ __align__(256) float g_AO[(size_t)NB*NS*ND];
__device__ __align__(256) float g_XP[(size_t)NM*ND];
__device__ __align__(256) float g_WP[(size_t)4*MM];

__device__ __forceinline__ float to_tf32(float x) {
    float r;
    asm("cvt.rna.tf32.f32 %0, %1;" : "=f"(r) : "f"(x));
    return r;
}

__device__ __forceinline__ void mma_tf32(float d[4], const uint32_t a[4],
                                         const uint32_t b[2]) {
    asm volatile(
        "mma.sync.aligned.m16n8k8.row.col.f32.tf32.tf32.f32 "
        "{%0,%1,%2,%3},{%4,%5,%6,%7},{%8,%9},{%0,%1,%2,%3};"
        : "+f"(d[0]), "+f"(d[1]), "+f"(d[2]), "+f"(d[3])
        : "r"(a[0]), "r"(a[1]), "r"(a[2]), "r"(a[3]),
          "r"(b[0]), "r"(b[1]));
}

__device__ __forceinline__ void cp16(void* dst, const void* src) {
    uint32_t d = (uint32_t)__cvta_generic_to_shared(dst);
    asm volatile("cp.async.cg.shared.global [%0], [%1], 16;" :: "r"(d), "l"(src));
}
__device__ __forceinline__ void cp_commit() {
    asm volatile("cp.async.commit_group;" ::: "memory");
}
__device__ __forceinline__ void cp_wait0() {
    asm volatile("cp.async.wait_group 0;" ::: "memory");
}
__device__ __forceinline__ void cp_wait1() {
    asm volatile("cp.async.wait_group 1;" ::: "memory");
}

// ---------------------------------------------------------------------------
// Prep: round x / weights to tf32 AND store K'-interleaved.
// Output float4 at (row, block blk, quad qq): t=qq>>1, R=qq&1 covers
// k' = t*8 + 4R + {0..3}  <-  k = blk*32 + 16R + t + {0,4,8,12}.
// ---------------------------------------------------------------------------
__global__ __launch_bounds__(256) void prep_perm(
    const float* __restrict__ x,
    const float* __restrict__ wq, const float* __restrict__ wk,
    const float* __restrict__ wv, const float* __restrict__ wo)
{
    const size_t XQ = (size_t)NM * ND / 4;
    const size_t WQ = (size_t)MM / 4;
    size_t i = (size_t)blockIdx.x * 256 + threadIdx.x;
    const float* src;
    float* dst;
    size_t o;
    if (i < XQ) {
        src = x; dst = g_XP; o = i;
    } else if (i < XQ + 4 * WQ) {
        size_t j = i - XQ;
        int w = (int)(j / WQ);
        o = j - (size_t)w * WQ;
        src = (w == 0) ? wq : (w == 1) ? wk : (w == 2) ? wv : wo;
        dst = g_WP + (size_t)w * MM;
    } else {
        return;
    }
    size_t row = o >> 8;          // 256 float4 per 1024-float row
    int q4  = (int)(o & 255);
    int blk = q4 >> 3;            // 32-float block
    int qq  = q4 & 7;
    int t = qq >> 1, R = qq & 1;
    const float* s = src + row * ND + blk * 32 + 16 * R + t;
    float4 v;
    v.x = to_tf32(s[0]);
    v.y = to_tf32(s[4]);
    v.z = to_tf32(s[8]);
    v.w = to_tf32(s[12]);
    ((float4*)dst)[o] = v;
}

// ---------------------------------------------------------------------------
// C = A @ W^T + bias, TF32 mma.sync.  A, W in K'-interleaved tf32 layout.
// CTA 128x128x32, 4 warps (2m x 2n), warp 64x64, 3-stage cp.async ring.
// Frag loads: one LDS.128 per row per 2 k8-steps (conflict-free, SSg=36).
// ---------------------------------------------------------------------------
#define SSg 36
#define GSTF (128*SSg)
#define STAGEF (2*GSTF)
#define GEMM_SMEM (3*STAGEF*4)       // 110592 B

__global__ __launch_bounds__(128, 2) void gemm_tf32(
    const float* __restrict__ b0, const float* __restrict__ b1,
    const float* __restrict__ b2, float* __restrict__ Cout,
    int amode, int fused, int cmode0)
{
    extern __shared__ float smg[];

    const float* A = amode ? g_AO : g_XP;
    int sel, nblk, cmode;
    const float* bias;
    if (fused) {
        sel  = blockIdx.x >> 3;
        nblk = blockIdx.x & 7;
        bias = (sel == 0) ? b0 : (sel == 1) ? b1 : b2;
        cmode = sel + 1;
    } else {
        sel = 3; nblk = blockIdx.x;
        bias = b0; cmode = cmode0;
    }
    const float* W = g_WP + (size_t)sel * MM;

    const int tid  = threadIdx.x;
    const int lane = tid & 31;
    const int wid  = tid >> 5;
    const int wm   = wid & 1;
    const int wn   = wid >> 1;
    const int m0   = blockIdx.y * 128;
    const int n0   = nblk * 128;
    const int g    = lane >> 2;
    const int tig  = lane & 3;

    float acc[4][8][4];
#pragma unroll
    for (int i = 0; i < 4; i++)
#pragma unroll
        for (int j = 0; j < 8; j++)
#pragma unroll
            for (int c = 0; c < 4; c++) acc[i][j][c] = 0.0f;

    const float* Ap = A + (size_t)m0 * ND;
    const float* Wp = W + (size_t)n0 * ND;

    auto loadStage = [&](int c) {
        float* As = smg + (c % 3) * STAGEF;
        float* Bs = As + GSTF;
#pragma unroll
        for (int i = 0; i < 8; i++) {
            int f = tid + i * 128;          // 0..1023
            int row = f >> 3, q = f & 7;
            cp16(&As[row * SSg + q * 4], Ap + (size_t)row * ND + c * 32 + q * 4);
            cp16(&Bs[row * SSg + q * 4], Wp + (size_t)row * ND + c * 32 + q * 4);
        }
    };

    constexpr int NCH = ND / 32;   // 32
    loadStage(0); cp_commit();
    loadStage(1); cp_commit();

    for (int c = 0; c < NCH; c++) {
        if (c + 1 < NCH) cp_wait1(); else cp_wait0();
        __syncthreads();
        if (c + 2 < NCH) { loadStage(c + 2); cp_commit(); }

        const float* As = smg + (c % 3) * STAGEF;
        const float* Bs = As + GSTF;

#pragma unroll
        for (int s2 = 0; s2 < 2; s2++) {
            float4 av[4][2];
#pragma unroll
            for (int mi = 0; mi < 4; mi++) {
                int r = wm * 64 + mi * 16 + g;
                av[mi][0] = *(const float4*)&As[r * SSg + tig * 8 + 4 * s2];
                av[mi][1] = *(const float4*)&As[(r + 8) * SSg + tig * 8 + 4 * s2];
            }
            float4 bv[8];
#pragma unroll
            for (int ni = 0; ni < 8; ni++)
                bv[ni] = *(const float4*)&Bs[(wn * 64 + ni * 8 + g) * SSg
                                             + tig * 8 + 4 * s2];
            // even k8-step (k = 16*s2 + {tig, tig+4})
#pragma unroll
            for (int mi = 0; mi < 4; mi++) {
                uint32_t a[4] = { __float_as_uint(av[mi][0].x),
                                  __float_as_uint(av[mi][1].x),
                                  __float_as_uint(av[mi][0].y),
                                  __float_as_uint(av[mi][1].y) };
#pragma unroll
                for (int ni = 0; ni < 8; ni++) {
                    uint32_t b[2] = { __float_as_uint(bv[ni].x),
                                      __float_as_uint(bv[ni].y) };
                    mma_tf32(acc[mi][ni], a, b);
                }
            }
            // odd k8-step (k = 16*s2 + 8 + {tig, tig+4})
#pragma unroll
            for (int mi = 0; mi < 4; mi++) {
                uint32_t a[4] = { __float_as_uint(av[mi][0].z),
                                  __float_as_uint(av[mi][1].z),
                                  __float_as_uint(av[mi][0].w),
                                  __float_as_uint(av[mi][1].w) };
#pragma unroll
                for (int ni = 0; ni < 8; ni++) {
                    uint32_t b[2] = { __float_as_uint(bv[ni].z),
                                      __float_as_uint(bv[ni].w) };
                    mma_tf32(acc[mi][ni], a, b);
                }
            }
        }
    }

    // ---- epilogue ----
#pragma unroll
    for (int mi = 0; mi < 4; mi++) {
#pragma unroll
        for (int ni = 0; ni < 8; ni++) {
#pragma unroll
            for (int c = 0; c < 4; c++) {
                int m = m0 + wm * 64 + mi * 16 + g + (c >> 1) * 8;
                int n = n0 + wn * 64 + ni * 8 + tig * 2 + (c & 1);
                float v = acc[mi][ni][c] + bias[n];
                if (cmode == 0) {
                    Cout[(size_t)m * ND + n] = v;
                } else {
                    int bb = m >> 11, ss = m & 2047;
                    int h = n >> 6, hd = n & 63;
                    if (cmode == 1) {
                        g_Q[(((size_t)(bb * NH + h)) * NS + ss) * HDIM + hd] = v;
                    } else if (cmode == 2) {
                        size_t off = (((size_t)(bb * NH + h)) * HDIM + hd) * NS
                                   + (ss & ~63) + ((ss & 7) * 8 + ((ss >> 3) & 7));
                        g_K[off] = to_tf32(v);
                    } else {
                        size_t off = (((size_t)(bb * NH + h)) * NS + ss) * HDIM
                                   + ((hd & 7) * 8 + (hd >> 3));
                        g_V[off] = to_tf32(v);
                    }
                }
            }
        }
    }
}

// ---------------------------------------------------------------------------
// Tensor-core flash attention, tf32 mma, causal.  Mainloop unchanged from R6;
// epilogue now writes g_AO in the K'-interleaved layout for the out-GEMM.
// ---------------------------------------------------------------------------
#define KSS 68
#define QROWS 128
#define FLASH_SMEM ((4*64*KSS + QROWS*KSS) * 4)   // 104448 B

__global__ __launch_bounds__(128, 2) void flash_attn_mma()
{
    extern __shared__ float sm[];
    float* KsA[2] = { sm,            sm + 64*KSS };
    float* VsA[2] = { sm + 2*64*KSS, sm + 3*64*KSS };
    float* Ps     = sm + 4*64*KSS;

    const int tid  = threadIdx.x;
    const int lane = tid & 31;
    const int wq   = tid >> 5;
    const int g    = lane >> 2;
    const int tig  = lane & 3;
    const int bh   = blockIdx.y;
    const int qt   = (int)gridDim.x - 1 - (int)blockIdx.x;
    const int q0   = qt * QROWS;

    const int tt[2]   = { wq, 7 - wq };
    const int trow[2] = { q0 + tt[0] * 16, q0 + tt[1] * 16 };

    const float* Qb = g_Q + (size_t)bh * NS * HDIM;
    const float* Kb = g_K + (size_t)bh * HDIM * NS;
    const float* Vb = g_V + (size_t)bh * NS * HDIM;

#pragma unroll
    for (int i = 0; i < 16; i++) {
        int f4 = tid + i * 128;
        int row = f4 >> 4, c = (f4 & 15) * 4;
        *(float4*)&Ps[row * KSS + c] =
            *(const float4*)(Qb + (size_t)(q0 + row) * HDIM + c);
    }
    __syncthreads();

    float qf[2][8][4];
#pragma unroll
    for (int mi = 0; mi < 2; mi++) {
        const float* Q0 = &Ps[(tt[mi] * 16 + g) * KSS];
        const float* Q1 = &Ps[(tt[mi] * 16 + g + 8) * KSS];
#pragma unroll
        for (int s = 0; s < 8; s++) {
            qf[mi][s][0] = to_tf32(Q0[8 * s + tig] * 0.125f);
            qf[mi][s][1] = to_tf32(Q1[8 * s + tig] * 0.125f);
            qf[mi][s][2] = to_tf32(Q0[8 * s + tig + 4] * 0.125f);
            qf[mi][s][3] = to_tf32(Q1[8 * s + tig + 4] * 0.125f);
        }
    }
    __syncthreads();

    const int ktmax = 2 * qt + 1;

    auto prefetch = [&](int t) {
        float* kd = KsA[t & 1];
        float* vd = VsA[t & 1];
        int kk0 = t * 64;
#pragma unroll
        for (int i = 0; i < 8; i++) {
            int f4 = tid + i * 128;
            int row = f4 >> 4, c = (f4 & 15) * 4;
            cp16(&kd[row * KSS + c], Kb + (size_t)row * NS + kk0 + c);
            cp16(&vd[row * KSS + c], Vb + (size_t)(kk0 + row) * HDIM + c);
        }
    };

    prefetch(0);
    cp_commit();

    float oacc[2][8][4];
#pragma unroll
    for (int mi = 0; mi < 2; mi++)
#pragma unroll
        for (int i = 0; i < 8; i++)
#pragma unroll
            for (int c = 0; c < 4; c++) oacc[mi][i][c] = 0.0f;
    float mx[2][2] = { {-INFINITY, -INFINITY}, {-INFINITY, -INFINITY} };
    float ls[2][2] = { {0.0f, 0.0f}, {0.0f, 0.0f} };
    float* Pw = Ps + (wq * 32) * KSS;

    for (int kt = 0; kt <= ktmax; kt++) {
        cp_wait0();
        __syncthreads();
        if (kt < ktmax) { prefetch(kt + 1); cp_commit(); }

        const int k0 = kt * 64;
        const bool act0 = (k0 <= trow[0] + 15);
        const bool act1 = (k0 <= trow[1] + 15);
        if (act1) {
            const float* K = KsA[kt & 1];
            const float* V = VsA[kt & 1];

            float sacc[2][8][4];
#pragma unroll
            for (int mi = 0; mi < 2; mi++)
#pragma unroll
                for (int i = 0; i < 8; i++)
#pragma unroll
                    for (int c = 0; c < 4; c++) sacc[mi][i][c] = 0.0f;

#pragma unroll
            for (int s = 0; s < 8; s++) {
                float k0a[8], k1a[8];
                const float* kr0 = &K[(8 * s + tig) * KSS + 8 * g];
                const float* kr1 = &K[(8 * s + tig + 4) * KSS + 8 * g];
                *(float4*)&k0a[0] = *(const float4*)&kr0[0];
                *(float4*)&k0a[4] = *(const float4*)&kr0[4];
                *(float4*)&k1a[0] = *(const float4*)&kr1[0];
                *(float4*)&k1a[4] = *(const float4*)&kr1[4];
#pragma unroll
                for (int mi = 0; mi < 2; mi++) {
                    if (mi == 0 && !act0) continue;
                    uint32_t a[4] = { __float_as_uint(qf[mi][s][0]),
                                      __float_as_uint(qf[mi][s][1]),
                                      __float_as_uint(qf[mi][s][2]),
                                      __float_as_uint(qf[mi][s][3]) };
#pragma unroll
                    for (int nt = 0; nt < 8; nt++) {
                        uint32_t b[2] = { __float_as_uint(k0a[nt]),
                                          __float_as_uint(k1a[nt]) };
                        mma_tf32(sacc[mi][nt], a, b);
                    }
                }
            }

#pragma unroll
            for (int mi = 0; mi < 2; mi++) {
                if (mi == 0 && !act0) continue;
                if (k0 + 63 > trow[mi]) {
                    int r0 = trow[mi] + g, r1 = r0 + 8;
#pragma unroll
                    for (int nt = 0; nt < 8; nt++) {
                        int c0 = k0 + 8 * nt + 2 * tig;
                        if (c0     > r0) sacc[mi][nt][0] = -INFINITY;
                        if (c0 + 1 > r0) sacc[mi][nt][1] = -INFINITY;
                        if (c0     > r1) sacc[mi][nt][2] = -INFINITY;
                        if (c0 + 1 > r1) sacc[mi][nt][3] = -INFINITY;
                    }
                }
            }

#pragma unroll
            for (int mi = 0; mi < 2; mi++) {
                if (mi == 0 && !act0) continue;
                float t0 = -INFINITY, t1 = -INFINITY;
#pragma unroll
                for (int nt = 0; nt < 8; nt++) {
                    t0 = fmaxf(t0, fmaxf(sacc[mi][nt][0], sacc[mi][nt][1]));
                    t1 = fmaxf(t1, fmaxf(sacc[mi][nt][2], sacc[mi][nt][3]));
                }
                t0 = fmaxf(t0, __shfl_xor_sync(0xffffffffu, t0, 1));
                t0 = fmaxf(t0, __shfl_xor_sync(0xffffffffu, t0, 2));
                t1 = fmaxf(t1, __shfl_xor_sync(0xffffffffu, t1, 1));
                t1 = fmaxf(t1, __shfl_xor_sync(0xffffffffu, t1, 2));
                float nm0 = fmaxf(mx[mi][0], t0), nm1 = fmaxf(mx[mi][1], t1);
                float corr0 = __expf(mx[mi][0] - nm0);
                float corr1 = __expf(mx[mi][1] - nm1);

                float* P0 = &Pw[(mi * 16 + g) * KSS];
                float* P1 = &Pw[(mi * 16 + g + 8) * KSS];
                float ps0 = 0.0f, ps1 = 0.0f;
#pragma unroll
                for (int nt = 0; nt < 8; nt++) {
                    float p0 = __expf(sacc[mi][nt][0] - nm0);
                    float p1 = __expf(sacc[mi][nt][1] - nm0);
                    float p2 = __expf(sacc[mi][nt][2] - nm1);
                    float p3 = __expf(sacc[mi][nt][3] - nm1);
                    ps0 += p0 + p1; ps1 += p2 + p3;
                    float2 lo = { to_tf32(p0), to_tf32(p1) };
                    float2 hi = { to_tf32(p2), to_tf32(p3) };
                    *(float2*)&P0[8 * nt + 2 * tig] = lo;
                    *(float2*)&P1[8 * nt + 2 * tig] = hi;
                }
                ps0 += __shfl_xor_sync(0xffffffffu, ps0, 1);
                ps0 += __shfl_xor_sync(0xffffffffu, ps0, 2);
                ps1 += __shfl_xor_sync(0xffffffffu, ps1, 1);
                ps1 += __shfl_xor_sync(0xffffffffu, ps1, 2);
                ls[mi][0] = ls[mi][0] * corr0 + ps0;
                ls[mi][1] = ls[mi][1] * corr1 + ps1;
                mx[mi][0] = nm0; mx[mi][1] = nm1;
#pragma unroll
                for (int nt = 0; nt < 8; nt++) {
                    oacc[mi][nt][0] *= corr0; oacc[mi][nt][1] *= corr0;
                    oacc[mi][nt][2] *= corr1; oacc[mi][nt][3] *= corr1;
                }
            }
            __syncwarp();

#pragma unroll
            for (int s = 0; s < 8; s++) {
                float v0a[8], v1a[8];
                const float* vr0 = &V[(8 * s + tig) * KSS + 8 * g];
                const float* vr1 = &V[(8 * s + tig + 4) * KSS + 8 * g];
                *(float4*)&v0a[0] = *(const float4*)&vr0[0];
                *(float4*)&v0a[4] = *(const float4*)&vr0[4];
                *(float4*)&v1a[0] = *(const float4*)&vr1[0];
                *(float4*)&v1a[4] = *(const float4*)&vr1[4];
#pragma unroll
                for (int mi = 0; mi < 2; mi++) {
                    if (mi == 0 && !act0) continue;
                    const float* P0 = &Pw[(mi * 16 + g) * KSS + 8 * s];
                    const float* P1 = &Pw[(mi * 16 + g + 8) * KSS + 8 * s];
                    uint32_t a[4] = { __float_as_uint(P0[tig]),
                                      __float_as_uint(P1[tig]),
                                      __float_as_uint(P0[tig + 4]),
                                      __float_as_uint(P1[tig + 4]) };
#pragma unroll
                    for (int nt = 0; nt < 8; nt++) {
                        uint32_t b[2] = { __float_as_uint(v0a[nt]),
                                          __float_as_uint(v1a[nt]) };
                        mma_tf32(oacc[mi][nt], a, b);
                    }
                }
            }
            __syncwarp();
        }
    }

    // ---- epilogue: K'-interleaved g_AO (feeds out-GEMM cp.async directly) ----
    int b = bh >> 4, h = bh & 15;
#pragma unroll
    for (int mi = 0; mi < 2; mi++) {
        float inv0 = 1.0f / ls[mi][0], inv1 = 1.0f / ls[mi][1];
        int row0 = trow[mi] + g;
        float* O0 = g_AO + ((size_t)(b * NS + row0)) * ND + h * HDIM;
        float* O1 = g_AO + ((size_t)(b * NS + row0 + 8)) * ND + h * HDIM;
#pragma unroll
        for (int nt = 0; nt < 8; nt++) {
            int s = nt & 3;
            int base = (nt >> 2) * 32;
#pragma unroll
            for (int ea = 0; ea < 2; ea++) {
                int jj = 2 * tig + ea;            // 0..7 within k8-group
                int t = jj & 3, e = jj >> 2;
                int jp = base + t * 8 + 2 * s + e;
                O0[jp] = to_tf32(oacc[mi][nt][ea] * inv0);
                O1[jp] = to_tf32(oacc[mi][nt][2 + ea] * inv1);
            }
        }
    }
}

// ---------------------------------------------------------------------------
extern "C" void kernel_launch(void* const* d_in, const int* in_sizes, int n_in,
                              void* d_out, int out_size)
{
    const float* x    = (const float*)d_in[0];
    const float* wq_w = (const float*)d_in[1];
    const float* wq_b = (const float*)d_in[2];
    const float* wk_w = (const float*)d_in[3];
    const float* wk_b = (const float*)d_in[4];
    const float* wv_w = (const float*)d_in[5];
    const float* wv_b = (const float*)d_in[6];
    const float* wo_w = (const float*)d_in[7];
    const float* wo_b = (const float*)d_in[8];
    float* out = (float*)d_out;

    cudaFuncSetAttribute(gemm_tf32, cudaFuncAttributeMaxDynamicSharedMemorySize,
                         GEMM_SMEM);
    cudaFuncSetAttribute(flash_attn_mma,
                         cudaFuncAttributeMaxDynamicSharedMemorySize, FLASH_SMEM);

    int prep_blocks = (int)(((size_t)NM * ND / 4 + (size_t)MM) / 256);
    prep_perm<<<prep_blocks, 256>>>(x, wq_w, wk_w, wv_w, wo_w);

    gemm_tf32<<<dim3(24, NM / 128), 128, GEMM_SMEM>>>(
        wq_b, wk_b, wv_b, nullptr, 0, 1, 0);

    flash_attn_mma<<<dim3(NS / QROWS, NB * NH), 128, FLASH_SMEM>>>();

    gemm_tf32<<<dim3(8, NM / 128), 128, GEMM_SMEM>>>(
        wo_b, nullptr, nullptr, out, 1, 0, 0);
}

// round 9
// speedup vs baseline: 1.0020x; 1.0020x over previous
#include <cuda_runtime.h>
#include <math.h>
#include <stdint.h>

#define NB 4
#define NS 2048
#define ND 1024
#define NH 16
#define HDIM 64
#define NM (NB*NS)   // 8192 rows
#define MM (ND*ND)

// Scratch (allocation-free rule: __device__ globals). ~182 MB total.
// g_Q: [bh][s][d]            (natural fp32)
// g_K: [bh][d][key]          key permuted per 64-block: pos=(k&7)*8+((k>>3)&7); tf32
// g_V: [bh][key][d']         d' = (d&7)*8 + (d>>3); tf32
// g_AO: attention out [B,S,D], tf32, K'-interleaved per 32-col block
// g_XP: tf32 x, K'-interleaved;  g_WP: tf32 Wq,Wk,Wv,Wo, K'-interleaved
// K'-interleave within each 32-float block: k = 8s + t + 4e  ->  k' = t*8 + 2s + e
__device__ __align__(256) float g_Q[(size_t)NB*NH*NS*HDIM];
__device__ __align__(256) float g_K[(size_t)NB*NH*NS*HDIM];
__device__ __align__(256) float g_V[(size_t)NB*NH*NS*HDIM];
__device__ __align__(256) float g_AO[(size_t)NB*NS*ND];
__device__ __align__(256) float g_XP[(size_t)NM*ND];
__device__ __align__(256) float g_WP[(size_t)4*MM];

__device__ __forceinline__ float to_tf32(float x) {
    float r;
    asm("cvt.rna.tf32.f32 %0, %1;" : "=f"(r) : "f"(x));
    return r;
}

__device__ __forceinline__ void mma_tf32(float d[4], const uint32_t a[4],
                                         const uint32_t b[2]) {
    asm volatile(
        "mma.sync.aligned.m16n8k8.row.col.f32.tf32.tf32.f32 "
        "{%0,%1,%2,%3},{%4,%5,%6,%7},{%8,%9},{%0,%1,%2,%3};"
        : "+f"(d[0]), "+f"(d[1]), "+f"(d[2]), "+f"(d[3])
        : "r"(a[0]), "r"(a[1]), "r"(a[2]), "r"(a[3]),
          "r"(b[0]), "r"(b[1]));
}

__device__ __forceinline__ void cp16(void* dst, const void* src) {
    uint32_t d = (uint32_t)__cvta_generic_to_shared(dst);
    asm volatile("cp.async.cg.shared.global [%0], [%1], 16;" :: "r"(d), "l"(src));
}
__device__ __forceinline__ void cp_commit() {
    asm volatile("cp.async.commit_group;" ::: "memory");
}
__device__ __forceinline__ void cp_wait0() {
    asm volatile("cp.async.wait_group 0;" ::: "memory");
}
__device__ __forceinline__ void cp_wait1() {
    asm volatile("cp.async.wait_group 1;" ::: "memory");
}

// ---------------------------------------------------------------------------
// Prep: round x / weights to tf32 AND store K'-interleaved.
// Output float4 at (row, block blk, quad qq): t=qq>>1, R=qq&1 covers
// k' = t*8 + 4R + {0..3}  <-  k = blk*32 + 16R + t + {0,4,8,12}.
// ---------------------------------------------------------------------------
__global__ __launch_bounds__(256) void prep_perm(
    const float* __restrict__ x,
    const float* __restrict__ wq, const float* __restrict__ wk,
    const float* __restrict__ wv, const float* __restrict__ wo)
{
    const size_t XQ = (size_t)NM * ND / 4;
    const size_t WQ = (size_t)MM / 4;
    size_t i = (size_t)blockIdx.x * 256 + threadIdx.x;
    const float* src;
    float* dst;
    size_t o;
    if (i < XQ) {
        src = x; dst = g_XP; o = i;
    } else if (i < XQ + 4 * WQ) {
        size_t j = i - XQ;
        int w = (int)(j / WQ);
        o = j - (size_t)w * WQ;
        src = (w == 0) ? wq : (w == 1) ? wk : (w == 2) ? wv : wo;
        dst = g_WP + (size_t)w * MM;
    } else {
        return;
    }
    size_t row = o >> 8;          // 256 float4 per 1024-float row
    int q4  = (int)(o & 255);
    int blk = q4 >> 3;            // 32-float block
    int qq  = q4 & 7;
    int t = qq >> 1, R = qq & 1;
    const float* s = src + row * ND + blk * 32 + 16 * R + t;
    float4 v;
    v.x = to_tf32(s[0]);
    v.y = to_tf32(s[4]);
    v.z = to_tf32(s[8]);
    v.w = to_tf32(s[12]);
    ((float4*)dst)[o] = v;
}

// ---------------------------------------------------------------------------
// C = A @ W^T + bias, TF32 mma.sync.  A, W in K'-interleaved tf32 layout.
// CTA 128x128x32, 4 warps (2m x 2n), warp 64x64, 3-stage cp.async ring.
// Frag loads: one LDS.128 per row per 2 k8-steps (conflict-free, SSg=36).
// ---------------------------------------------------------------------------
#define SSg 36
#define GSTF (128*SSg)
#define STAGEF (2*GSTF)
#define GEMM_SMEM (3*STAGEF*4)       // 110592 B

__global__ __launch_bounds__(128, 2) void gemm_tf32(
    const float* __restrict__ b0, const float* __restrict__ b1,
    const float* __restrict__ b2, float* __restrict__ Cout,
    int amode, int fused, int cmode0)
{
    extern __shared__ float smg[];

    const float* A = amode ? g_AO : g_XP;
    int sel, nblk, cmode;
    const float* bias;
    if (fused) {
        sel  = blockIdx.x >> 3;
        nblk = blockIdx.x & 7;
        bias = (sel == 0) ? b0 : (sel == 1) ? b1 : b2;
        cmode = sel + 1;
    } else {
        sel = 3; nblk = blockIdx.x;
        bias = b0; cmode = cmode0;
    }
    const float* W = g_WP + (size_t)sel * MM;

    const int tid  = threadIdx.x;
    const int lane = tid & 31;
    const int wid  = tid >> 5;
    const int wm   = wid & 1;
    const int wn   = wid >> 1;
    const int m0   = blockIdx.y * 128;
    const int n0   = nblk * 128;
    const int g    = lane >> 2;
    const int tig  = lane & 3;

    float acc[4][8][4];
#pragma unroll
    for (int i = 0; i < 4; i++)
#pragma unroll
        for (int j = 0; j < 8; j++)
#pragma unroll
            for (int c = 0; c < 4; c++) acc[i][j][c] = 0.0f;

    const float* Ap = A + (size_t)m0 * ND;
    const float* Wp = W + (size_t)n0 * ND;

    auto loadStage = [&](int c) {
        float* As = smg + (c % 3) * STAGEF;
        float* Bs = As + GSTF;
#pragma unroll
        for (int i = 0; i < 8; i++) {
            int f = tid + i * 128;          // 0..1023
            int row = f >> 3, q = f & 7;
            cp16(&As[row * SSg + q * 4], Ap + (size_t)row * ND + c * 32 + q * 4);
            cp16(&Bs[row * SSg + q * 4], Wp + (size_t)row * ND + c * 32 + q * 4);
        }
    };

    constexpr int NCH = ND / 32;   // 32
    loadStage(0); cp_commit();
    loadStage(1); cp_commit();

    for (int c = 0; c < NCH; c++) {
        if (c + 1 < NCH) cp_wait1(); else cp_wait0();
        __syncthreads();
        if (c + 2 < NCH) { loadStage(c + 2); cp_commit(); }

        const float* As = smg + (c % 3) * STAGEF;
        const float* Bs = As + GSTF;

#pragma unroll
        for (int s2 = 0; s2 < 2; s2++) {
            float4 av[4][2];
#pragma unroll
            for (int mi = 0; mi < 4; mi++) {
                int r = wm * 64 + mi * 16 + g;
                av[mi][0] = *(const float4*)&As[r * SSg + tig * 8 + 4 * s2];
                av[mi][1] = *(const float4*)&As[(r + 8) * SSg + tig * 8 + 4 * s2];
            }
            float4 bv[8];
#pragma unroll
            for (int ni = 0; ni < 8; ni++)
                bv[ni] = *(const float4*)&Bs[(wn * 64 + ni * 8 + g) * SSg
                                             + tig * 8 + 4 * s2];
            // even k8-step (k = 16*s2 + {tig, tig+4})
#pragma unroll
            for (int mi = 0; mi < 4; mi++) {
                uint32_t a[4] = { __float_as_uint(av[mi][0].x),
                                  __float_as_uint(av[mi][1].x),
                                  __float_as_uint(av[mi][0].y),
                                  __float_as_uint(av[mi][1].y) };
#pragma unroll
                for (int ni = 0; ni < 8; ni++) {
                    uint32_t b[2] = { __float_as_uint(bv[ni].x),
                                      __float_as_uint(bv[ni].y) };
                    mma_tf32(acc[mi][ni], a, b);
                }
            }
            // odd k8-step (k = 16*s2 + 8 + {tig, tig+4})
#pragma unroll
            for (int mi = 0; mi < 4; mi++) {
                uint32_t a[4] = { __float_as_uint(av[mi][0].z),
                                  __float_as_uint(av[mi][1].z),
                                  __float_as_uint(av[mi][0].w),
                                  __float_as_uint(av[mi][1].w) };
#pragma unroll
                for (int ni = 0; ni < 8; ni++) {
                    uint32_t b[2] = { __float_as_uint(bv[ni].z),
                                      __float_as_uint(bv[ni].w) };
                    mma_tf32(acc[mi][ni], a, b);
                }
            }
        }
    }

    // ---- epilogue ----
#pragma unroll
    for (int mi = 0; mi < 4; mi++) {
#pragma unroll
        for (int ni = 0; ni < 8; ni++) {
#pragma unroll
            for (int c = 0; c < 4; c++) {
                int m = m0 + wm * 64 + mi * 16 + g + (c >> 1) * 8;
                int n = n0 + wn * 64 + ni * 8 + tig * 2 + (c & 1);
                float v = acc[mi][ni][c] + bias[n];
                if (cmode == 0) {
                    Cout[(size_t)m * ND + n] = v;
                } else {
                    int bb = m >> 11, ss = m & 2047;
                    int h = n >> 6, hd = n & 63;
                    if (cmode == 1) {
                        g_Q[(((size_t)(bb * NH + h)) * NS + ss) * HDIM + hd] = v;
                    } else if (cmode == 2) {
                        size_t off = (((size_t)(bb * NH + h)) * HDIM + hd) * NS
                                   + (ss & ~63) + ((ss & 7) * 8 + ((ss >> 3) & 7));
                        g_K[off] = to_tf32(v);
                    } else {
                        size_t off = (((size_t)(bb * NH + h)) * NS + ss) * HDIM
                                   + ((hd & 7) * 8 + (hd >> 3));
                        g_V[off] = to_tf32(v);
                    }
                }
            }
        }
    }
}

// ---------------------------------------------------------------------------
// Tensor-core flash attention, tf32 mma, causal.  Mainloop unchanged from R6;
// epilogue now writes g_AO in the K'-interleaved layout for the out-GEMM.
// ---------------------------------------------------------------------------
#define KSS 68
#define QROWS 128
#define FLASH_SMEM ((4*64*KSS + QROWS*KSS) * 4)   // 104448 B

__global__ __launch_bounds__(128, 2) void flash_attn_mma()
{
    extern __shared__ float sm[];
    float* KsA[2] = { sm,            sm + 64*KSS };
    float* VsA[2] = { sm + 2*64*KSS, sm + 3*64*KSS };
    float* Ps     = sm + 4*64*KSS;

    const int tid  = threadIdx.x;
    const int lane = tid & 31;
    const int wq   = tid >> 5;
    const int g    = lane >> 2;
    const int tig  = lane & 3;
    const int bh   = blockIdx.y;
    const int qt   = (int)gridDim.x - 1 - (int)blockIdx.x;
    const int q0   = qt * QROWS;

    const int tt[2]   = { wq, 7 - wq };
    const int trow[2] = { q0 + tt[0] * 16, q0 + tt[1] * 16 };

    const float* Qb = g_Q + (size_t)bh * NS * HDIM;
    const float* Kb = g_K + (size_t)bh * HDIM * NS;
    const float* Vb = g_V + (size_t)bh * NS * HDIM;

#pragma unroll
    for (int i = 0; i < 16; i++) {
        int f4 = tid + i * 128;
        int row = f4 >> 4, c = (f4 & 15) * 4;
        *(float4*)&Ps[row * KSS + c] =
            *(const float4*)(Qb + (size_t)(q0 + row) * HDIM + c);
    }
    __syncthreads();

    float qf[2][8][4];
#pragma unroll
    for (int mi = 0; mi < 2; mi++) {
        const float* Q0 = &Ps[(tt[mi] * 16 + g) * KSS];
        const float* Q1 = &Ps[(tt[mi] * 16 + g + 8) * KSS];
#pragma unroll
        for (int s = 0; s < 8; s++) {
            qf[mi][s][0] = to_tf32(Q0[8 * s + tig] * 0.125f);
            qf[mi][s][1] = to_tf32(Q1[8 * s + tig] * 0.125f);
            qf[mi][s][2] = to_tf32(Q0[8 * s + tig + 4] * 0.125f);
            qf[mi][s][3] = to_tf32(Q1[8 * s + tig + 4] * 0.125f);
        }
    }
    __syncthreads();

    const int ktmax = 2 * qt + 1;

    auto prefetch = [&](int t) {
        float* kd = KsA[t & 1];
        float* vd = VsA[t & 1];
        int kk0 = t * 64;
#pragma unroll
        for (int i = 0; i < 8; i++) {
            int f4 = tid + i * 128;
            int row = f4 >> 4, c = (f4 & 15) * 4;
            cp16(&kd[row * KSS + c], Kb + (size_t)row * NS + kk0 + c);
            cp16(&vd[row * KSS + c], Vb + (size_t)(kk0 + row) * HDIM + c);
        }
    };

    prefetch(0);
    cp_commit();

    float oacc[2][8][4];
#pragma unroll
    for (int mi = 0; mi < 2; mi++)
#pragma unroll
        for (int i = 0; i < 8; i++)
#pragma unroll
            for (int c = 0; c < 4; c++) oacc[mi][i][c] = 0.0f;
    float mx[2][2] = { {-INFINITY, -INFINITY}, {-INFINITY, -INFINITY} };
    float ls[2][2] = { {0.0f, 0.0f}, {0.0f, 0.0f} };
    float* Pw = Ps + (wq * 32) * KSS;

    for (int kt = 0; kt <= ktmax; kt++) {
        cp_wait0();
        __syncthreads();
        if (kt < ktmax) { prefetch(kt + 1); cp_commit(); }

        const int k0 = kt * 64;
        const bool act0 = (k0 <= trow[0] + 15);
        const bool act1 = (k0 <= trow[1] + 15);
        if (act1) {
            const float* K = KsA[kt & 1];
            const float* V = VsA[kt & 1];

            float sacc[2][8][4];
#pragma unroll
            for (int mi = 0; mi < 2; mi++)
#pragma unroll
                for (int i = 0; i < 8; i++)
#pragma unroll
                    for (int c = 0; c < 4; c++) sacc[mi][i][c] = 0.0f;

#pragma unroll
            for (int s = 0; s < 8; s++) {
                float k0a[8], k1a[8];
                const float* kr0 = &K[(8 * s + tig) * KSS + 8 * g];
                const float* kr1 = &K[(8 * s + tig + 4) * KSS + 8 * g];
                *(float4*)&k0a[0] = *(const float4*)&kr0[0];
                *(float4*)&k0a[4] = *(const float4*)&kr0[4];
                *(float4*)&k1a[0] = *(const float4*)&kr1[0];
                *(float4*)&k1a[4] = *(const float4*)&kr1[4];
#pragma unroll
                for (int mi = 0; mi < 2; mi++) {
                    if (mi == 0 && !act0) continue;
                    uint32_t a[4] = { __float_as_uint(qf[mi][s][0]),
                                      __float_as_uint(qf[mi][s][1]),
                                      __float_as_uint(qf[mi][s][2]),
                                      __float_as_uint(qf[mi][s][3]) };
#pragma unroll
                    for (int nt = 0; nt < 8; nt++) {
                        uint32_t b[2] = { __float_as_uint(k0a[nt]),
                                          __float_as_uint(k1a[nt]) };
                        mma_tf32(sacc[mi][nt], a, b);
                    }
                }
            }

#pragma unroll
            for (int mi = 0; mi < 2; mi++) {
                if (mi == 0 && !act0) continue;
                if (k0 + 63 > trow[mi]) {
                    int r0 = trow[mi] + g, r1 = r0 + 8;
#pragma unroll
                    for (int nt = 0; nt < 8; nt++) {
                        int c0 = k0 + 8 * nt + 2 * tig;
                        if (c0     > r0) sacc[mi][nt][0] = -INFINITY;
                        if (c0 + 1 > r0) sacc[mi][nt][1] = -INFINITY;
                        if (c0     > r1) sacc[mi][nt][2] = -INFINITY;
                        if (c0 + 1 > r1) sacc[mi][nt][3] = -INFINITY;
                    }
                }
            }

#pragma unroll
            for (int mi = 0; mi < 2; mi++) {
                if (mi == 0 && !act0) continue;
                float t0 = -INFINITY, t1 = -INFINITY;
#pragma unroll
                for (int nt = 0; nt < 8; nt++) {
                    t0 = fmaxf(t0, fmaxf(sacc[mi][nt][0], sacc[mi][nt][1]));
                    t1 = fmaxf(t1, fmaxf(sacc[mi][nt][2], sacc[mi][nt][3]));
                }
                t0 = fmaxf(t0, __shfl_xor_sync(0xffffffffu, t0, 1));
                t0 = fmaxf(t0, __shfl_xor_sync(0xffffffffu, t0, 2));
                t1 = fmaxf(t1, __shfl_xor_sync(0xffffffffu, t1, 1));
                t1 = fmaxf(t1, __shfl_xor_sync(0xffffffffu, t1, 2));
                float nm0 = fmaxf(mx[mi][0], t0), nm1 = fmaxf(mx[mi][1], t1);
                float corr0 = __expf(mx[mi][0] - nm0);
                float corr1 = __expf(mx[mi][1] - nm1);

                float* P0 = &Pw[(mi * 16 + g) * KSS];
                float* P1 = &Pw[(mi * 16 + g + 8) * KSS];
                float ps0 = 0.0f, ps1 = 0.0f;
#pragma unroll
                for (int nt = 0; nt < 8; nt++) {
                    float p0 = __expf(sacc[mi][nt][0] - nm0);
                    float p1 = __expf(sacc[mi][nt][1] - nm0);
                    float p2 = __expf(sacc[mi][nt][2] - nm1);
                    float p3 = __expf(sacc[mi][nt][3] - nm1);
                    ps0 += p0 + p1; ps1 += p2 + p3;
                    float2 lo = { to_tf32(p0), to_tf32(p1) };
                    float2 hi = { to_tf32(p2), to_tf32(p3) };
                    *(float2*)&P0[8 * nt + 2 * tig] = lo;
                    *(float2*)&P1[8 * nt + 2 * tig] = hi;
                }
                ps0 += __shfl_xor_sync(0xffffffffu, ps0, 1);
                ps0 += __shfl_xor_sync(0xffffffffu, ps0, 2);
                ps1 += __shfl_xor_sync(0xffffffffu, ps1, 1);
                ps1 += __shfl_xor_sync(0xffffffffu, ps1, 2);
                ls[mi][0] = ls[mi][0] * corr0 + ps0;
                ls[mi][1] = ls[mi][1] * corr1 + ps1;
                mx[mi][0] = nm0; mx[mi][1] = nm1;
#pragma unroll
                for (int nt = 0; nt < 8; nt++) {
                    oacc[mi][nt][0] *= corr0; oacc[mi][nt][1] *= corr0;
                    oacc[mi][nt][2] *= corr1; oacc[mi][nt][3] *= corr1;
                }
            }
            __syncwarp();

#pragma unroll
            for (int s = 0; s < 8; s++) {
                float v0a[8], v1a[8];
                const float* vr0 = &V[(8 * s + tig) * KSS + 8 * g];
                const float* vr1 = &V[(8 * s + tig + 4) * KSS + 8 * g];
                *(float4*)&v0a[0] = *(const float4*)&vr0[0];
                *(float4*)&v0a[4] = *(const float4*)&vr0[4];
                *(float4*)&v1a[0] = *(const float4*)&vr1[0];
                *(float4*)&v1a[4] = *(const float4*)&vr1[4];
#pragma unroll
                for (int mi = 0; mi < 2; mi++) {
                    if (mi == 0 && !act0) continue;
                    const float* P0 = &Pw[(mi * 16 + g) * KSS + 8 * s];
                    const float* P1 = &Pw[(mi * 16 + g + 8) * KSS + 8 * s];
                    uint32_t a[4] = { __float_as_uint(P0[tig]),
                                      __float_as_uint(P1[tig]),
                                      __float_as_uint(P0[tig + 4]),
                                      __float_as_uint(P1[tig + 4]) };
#pragma unroll
                    for (int nt = 0; nt < 8; nt++) {
                        uint32_t b[2] = { __float_as_uint(v0a[nt]),
                                          __float_as_uint(v1a[nt]) };
                        mma_tf32(oacc[mi][nt], a, b);
                    }
                }
            }
            __syncwarp();
        }
    }

    // ---- epilogue: K'-interleaved g_AO (feeds out-GEMM cp.async directly) ----
    int b = bh >> 4, h = bh & 15;
#pragma unroll
    for (int mi = 0; mi < 2; mi++) {
        float inv0 = 1.0f / ls[mi][0], inv1 = 1.0f / ls[mi][1];
        int row0 = trow[mi] + g;
        float* O0 = g_AO + ((size_t)(b * NS + row0)) * ND + h * HDIM;
        float* O1 = g_AO + ((size_t)(b * NS + row0 + 8)) * ND + h * HDIM;
#pragma unroll
        for (int nt = 0; nt < 8; nt++) {
            int s = nt & 3;
            int base = (nt >> 2) * 32;
#pragma unroll
            for (int ea = 0; ea < 2; ea++) {
                int jj = 2 * tig + ea;            // 0..7 within k8-group
                int t = jj & 3, e = jj >> 2;
                int jp = base + t * 8 + 2 * s + e;
                O0[jp] = to_tf32(oacc[mi][nt][ea] * inv0);
                O1[jp] = to_tf32(oacc[mi][nt][2 + ea] * inv1);
            }
        }
    }
}

// ---------------------------------------------------------------------------
extern "C" void kernel_launch(void* const* d_in, const int* in_sizes, int n_in,
                              void* d_out, int out_size)
{
    const float* x    = (const float*)d_in[0];
    const float* wq_w = (const float*)d_in[1];
    const float* wq_b = (const float*)d_in[2];
    const float* wk_w = (const float*)d_in[3];
    const float* wk_b = (const float*)d_in[4];
    const float* wv_w = (const float*)d_in[5];
    const float* wv_b = (const float*)d_in[6];
    const float* wo_w = (const float*)d_in[7];
    const float* wo_b = (const float*)d_in[8];
    float* out = (float*)d_out;

    cudaFuncSetAttribute(gemm_tf32, cudaFuncAttributeMaxDynamicSharedMemorySize,
                         GEMM_SMEM);
    cudaFuncSetAttribute(flash_attn_mma,
                         cudaFuncAttributeMaxDynamicSharedMemorySize, FLASH_SMEM);

    int prep_blocks = (int)(((size_t)NM * ND / 4 + (size_t)MM) / 256);
    prep_perm<<<prep_blocks, 256>>>(x, wq_w, wk_w, wv_w, wo_w);

    gemm_tf32<<<dim3(24, NM / 128), 128, GEMM_SMEM>>>(
        wq_b, wk_b, wv_b, nullptr, 0, 1, 0);

    flash_attn_mma<<<dim3(NS / QROWS, NB * NH), 128, FLASH_SMEM>>>();

    gemm_tf32<<<dim3(8, NM / 128), 128, GEMM_SMEM>>>(
        wo_b, nullptr, nullptr, out, 1, 0, 0);
}

// round 10
// speedup vs baseline: 2.0116x; 2.0075x over previous
#include <cuda_runtime.h>
#include <cuda_fp16.h>
#include <math.h>
#include <stdint.h>

#define NB 4
#define NS 2048
#define ND 1024
#define NH 16
#define HDIM 64
#define NM (NB*NS)
#define MM (ND*ND)

// fp16 scratch (~58 MB), all k'-interleaved per 32-block:
//   k = 16u+8v+2t+w  ->  k' = 8t+4u+2v+w
// g_XP/g_WP/g_AO: [row][1024]
// g_Q: [bh][s][64]  (pre-scaled by 0.125, d interleaved)
// g_K: [bh][key][64] (d interleaved)
// g_V: [bh][d][2048] (key interleaved)
__device__ __align__(256) __half g_Q [(size_t)NB*NH*NS*HDIM];
__device__ __align__(256) __half g_K [(size_t)NB*NH*NS*HDIM];
__device__ __align__(256) __half g_V [(size_t)NB*NH*NS*HDIM];
__device__ __align__(256) __half g_AO[(size_t)NM*ND];
__device__ __align__(256) __half g_XP[(size_t)NM*ND];
__device__ __align__(256) __half g_WP[(size_t)4*MM];

__device__ __forceinline__ void mma_f16(float d[4], uint32_t a0, uint32_t a1,
                                        uint32_t a2, uint32_t a3,
                                        uint32_t b0, uint32_t b1) {
    asm volatile(
        "mma.sync.aligned.m16n8k16.row.col.f32.f16.f16.f32 "
        "{%0,%1,%2,%3},{%4,%5,%6,%7},{%8,%9},{%0,%1,%2,%3};"
        : "+f"(d[0]), "+f"(d[1]), "+f"(d[2]), "+f"(d[3])
        : "r"(a0), "r"(a1), "r"(a2), "r"(a3), "r"(b0), "r"(b1));
}
__device__ __forceinline__ uint32_t h2u(float a, float b) {
    __half2 h = __halves2half2(__float2half_rn(a), __float2half_rn(b));
    return *(uint32_t*)&h;
}
// interleaved position of element k (within any 32-block)
__device__ __forceinline__ int kpos(int k) {
    return (k & ~31) | (8*((k>>1)&3) + 4*((k>>4)&1) + 2*((k>>3)&1) + (k&1));
}
__device__ __forceinline__ void cp16(void* dst, const void* src) {
    uint32_t d = (uint32_t)__cvta_generic_to_shared(dst);
    asm volatile("cp.async.cg.shared.global [%0], [%1], 16;" :: "r"(d), "l"(src));
}
__device__ __forceinline__ void cp_commit() {
    asm volatile("cp.async.commit_group;" ::: "memory");
}
__device__ __forceinline__ void cp_wait0() {
    asm volatile("cp.async.wait_group 0;" ::: "memory");
}
__device__ __forceinline__ void cp_wait1() {
    asm volatile("cp.async.wait_group 1;" ::: "memory");
}

// ---------------------------------------------------------------------------
// Prep: fp16-round x and 4 weights into k'-interleaved layout.
// One thread = one 8-half chunk (row, blk, t) <- k = 32blk + {2t,2t+1, +8, +16, +24}.
// ---------------------------------------------------------------------------
__global__ __launch_bounds__(256) void prep(
    const float* __restrict__ x,
    const float* __restrict__ wq, const float* __restrict__ wk,
    const float* __restrict__ wv, const float* __restrict__ wo)
{
    const size_t XC = (size_t)NM * 128;
    const size_t WC = (size_t)ND * 128;
    size_t i = (size_t)blockIdx.x * 256 + threadIdx.x;
    const float* src; __half* dst; size_t o;
    if (i < XC) { src = x; dst = g_XP; o = i; }
    else if (i < XC + 4 * WC) {
        size_t j = i - XC;
        int w = (int)(j / WC);
        o = j - (size_t)w * WC;
        src = (w == 0) ? wq : (w == 1) ? wk : (w == 2) ? wv : wo;
        dst = g_WP + (size_t)w * MM;
    } else return;
    size_t row = o >> 7;
    int c = (int)(o & 127), blk = c >> 2, t = c & 3;
    const float* s = src + row * ND + blk * 32 + 2 * t;
    uint4 v;
    v.x = h2u(s[0],  s[1]);
    v.y = h2u(s[8],  s[9]);
    v.z = h2u(s[16], s[17]);
    v.w = h2u(s[24], s[25]);
    *(uint4*)(dst + row * ND + blk * 32 + t * 8) = v;
}

// ---------------------------------------------------------------------------
// C = A @ W^T + bias, fp16 m16n8k16.  CTA 128x128x32, 4 warps (2m x 2n),
// warp 64x64, 3-stage cp.async ring. Per chunk/warp: 16 LDS.128, 64 mma.
// ---------------------------------------------------------------------------
#define GEMM_SMEM 49152   // 3 stages x (A 4096 + B 4096 halves) x 2B

__global__ __launch_bounds__(128, 2) void gemm_f16(
    const float* __restrict__ bq, const float* __restrict__ bk,
    const float* __restrict__ bv, float* __restrict__ Cout,
    int amode, int fused, int cmode0)
{
    extern __shared__ __half smh[];
    const __half* A = amode ? g_AO : g_XP;
    int sel, nblk, cmode;
    const float* bias;
    if (fused) {
        sel  = blockIdx.x >> 3;
        nblk = blockIdx.x & 7;
        bias = (sel == 0) ? bq : (sel == 1) ? bk : bv;
        cmode = sel + 1;
    } else { sel = 3; nblk = blockIdx.x; bias = bq; cmode = cmode0; }
    const __half* W = g_WP + (size_t)sel * MM;

    const int tid = threadIdx.x, lane = tid & 31, wid = tid >> 5;
    const int wm = wid & 1, wn = wid >> 1;
    const int m0 = blockIdx.y * 128, n0 = nblk * 128;
    const int g = lane >> 2, t = lane & 3;

    float acc[4][8][4];
#pragma unroll
    for (int i = 0; i < 4; i++)
#pragma unroll
        for (int j = 0; j < 8; j++)
#pragma unroll
            for (int c = 0; c < 4; c++) acc[i][j][c] = 0.0f;

    const __half* Ap = A + (size_t)m0 * ND;
    const __half* Wp = W + (size_t)n0 * ND;

    auto loadStage = [&](int c) {
        __half* As = smh + (c % 3) * 8192;
        __half* Bs = As + 4096;
#pragma unroll
        for (int i = 0; i < 4; i++) {
            int f = tid + i * 128;           // 0..511
            int row = f >> 2, q = f & 3;     // 4 chunks (32 halves) per row
            cp16(As + row * 32 + q * 8, Ap + (size_t)row * ND + c * 32 + q * 8);
            cp16(Bs + row * 32 + q * 8, Wp + (size_t)row * ND + c * 32 + q * 8);
        }
    };

    loadStage(0); cp_commit();
    loadStage(1); cp_commit();

    for (int c = 0; c < 32; c++) {
        if (c + 1 < 32) cp_wait1(); else cp_wait0();
        __syncthreads();
        if (c + 2 < 32) { loadStage(c + 2); cp_commit(); }

        const __half* As = smh + (c % 3) * 8192;
        const __half* Bs = As + 4096;

        uint4 alo[4], ahi[4];
#pragma unroll
        for (int mi = 0; mi < 4; mi++) {
            int r = wm * 64 + mi * 16 + g;
            alo[mi] = *(const uint4*)(As + r * 32 + t * 8);
            ahi[mi] = *(const uint4*)(As + (r + 8) * 32 + t * 8);
        }
        uint4 bv4[8];
#pragma unroll
        for (int ni = 0; ni < 8; ni++)
            bv4[ni] = *(const uint4*)(Bs + (wn * 64 + ni * 8 + g) * 32 + t * 8);

#pragma unroll
        for (int mi = 0; mi < 4; mi++)
#pragma unroll
            for (int ni = 0; ni < 8; ni++) {
                mma_f16(acc[mi][ni], alo[mi].x, ahi[mi].x, alo[mi].y, ahi[mi].y,
                        bv4[ni].x, bv4[ni].y);
                mma_f16(acc[mi][ni], alo[mi].z, ahi[mi].z, alo[mi].w, ahi[mi].w,
                        bv4[ni].z, bv4[ni].w);
            }
    }

    // ---- epilogue ----
#pragma unroll
    for (int mi = 0; mi < 4; mi++) {
#pragma unroll
        for (int ni = 0; ni < 8; ni++) {
            int mlo = m0 + wm * 64 + mi * 16 + g;
            int n = n0 + wn * 64 + ni * 8 + 2 * t;
            float2 bl = *(const float2*)&bias[n];
            float cc[4] = { acc[mi][ni][0] + bl.x, acc[mi][ni][1] + bl.y,
                            acc[mi][ni][2] + bl.x, acc[mi][ni][3] + bl.y };
            if (cmode == 0) {
                *(float2*)&Cout[(size_t)mlo * ND + n] = make_float2(cc[0], cc[1]);
                *(float2*)&Cout[(size_t)(mlo + 8) * ND + n] = make_float2(cc[2], cc[3]);
            } else {
                int h = n >> 6, hd = n & 63;
#pragma unroll
                for (int rr = 0; rr < 2; rr++) {
                    int m = mlo + 8 * rr;
                    int bb = m >> 11, ss = m & 2047;
                    int bhh = bb * NH + h;
                    float ca = cc[2 * rr], cb = cc[2 * rr + 1];
                    if (cmode == 1) {
                        __half2 hv = __halves2half2(__float2half_rn(ca * 0.125f),
                                                    __float2half_rn(cb * 0.125f));
                        *(__half2*)&g_Q[((size_t)bhh * NS + ss) * HDIM + kpos(hd)] = hv;
                    } else if (cmode == 2) {
                        __half2 hv = __halves2half2(__float2half_rn(ca),
                                                    __float2half_rn(cb));
                        *(__half2*)&g_K[((size_t)bhh * NS + ss) * HDIM + kpos(hd)] = hv;
                    } else {
                        int p = kpos(ss);
                        g_V[((size_t)bhh * HDIM + hd) * NS + p] = __float2half_rn(ca);
                        g_V[((size_t)bhh * HDIM + hd + 1) * NS + p] = __float2half_rn(cb);
                    }
                }
            }
        }
    }
}

// ---------------------------------------------------------------------------
// fp16 flash attention, causal. CTA: 128 q-rows of one (b,h); 4 warps, warp
// owns m16 tiles {wq, 7-wq}. K-tiles of 64, double-buffered cp.async.
// Q frags from global; P register-resident (QK D-frag == PV A-frag mapping).
// ---------------------------------------------------------------------------
#define FLASH_SMEM 32768   // 2xK(4096h) + 2xV(4096h)

__global__ __launch_bounds__(128, 2) void flash_attn_f16()
{
    extern __shared__ __half smf[];
    const int tid = threadIdx.x, lane = tid & 31, wq = tid >> 5;
    const int g = lane >> 2, t = lane & 3;
    const int bh = blockIdx.y;
    const int qt = (int)gridDim.x - 1 - (int)blockIdx.x;
    const int q0 = qt * 128;
    const int trow0 = q0 + wq * 16, trow1 = q0 + (7 - wq) * 16;
    const int xorsw = (g & 1) << 2;

    const __half* Kb = g_K + (size_t)bh * NS * HDIM;
    const __half* Vb = g_V + (size_t)bh * HDIM * NS;

    // ---- Q fragments (direct from global; 8 LDG.128) ----
    uint32_t qf[2][4][4];
    {
        const int rows[2] = { trow0, trow1 };
#pragma unroll
        for (int mi = 0; mi < 2; mi++) {
            const __half* p0 = g_Q + ((size_t)bh * NS + rows[mi] + g) * HDIM;
            const __half* p1 = g_Q + ((size_t)bh * NS + rows[mi] + g + 8) * HDIM;
            uint4 a0 = *(const uint4*)(p0 + t * 8);
            uint4 a1 = *(const uint4*)(p1 + t * 8);
            uint4 b0 = *(const uint4*)(p0 + 32 + t * 8);
            uint4 b1 = *(const uint4*)(p1 + 32 + t * 8);
            qf[mi][0][0]=a0.x; qf[mi][0][1]=a1.x; qf[mi][0][2]=a0.y; qf[mi][0][3]=a1.y;
            qf[mi][1][0]=a0.z; qf[mi][1][1]=a1.z; qf[mi][1][2]=a0.w; qf[mi][1][3]=a1.w;
            qf[mi][2][0]=b0.x; qf[mi][2][1]=b1.x; qf[mi][2][2]=b0.y; qf[mi][2][3]=b1.y;
            qf[mi][3][0]=b0.z; qf[mi][3][1]=b1.z; qf[mi][3][2]=b0.w; qf[mi][3][3]=b1.w;
        }
    }

    auto prefetch = [&](int kt) {
        __half* Ks = smf + (kt & 1) * 4096;
        __half* Vs = smf + 8192 + (kt & 1) * 4096;
        int kk0 = kt * 64;
#pragma unroll
        for (int i = 0; i < 4; i++) {
            int cid = tid + i * 128;       // 0..511
            int row = cid >> 3, c = cid & 7;
            int sw = c ^ ((row & 1) << 2);
            cp16(Ks + row * 64 + sw * 8, Kb + (size_t)(kk0 + row) * HDIM + c * 8);
            cp16(Vs + row * 64 + sw * 8, Vb + (size_t)row * NS + kk0 + c * 8);
        }
    };

    prefetch(0); cp_commit();

    float oacc[2][8][4];
#pragma unroll
    for (int mi = 0; mi < 2; mi++)
#pragma unroll
        for (int i = 0; i < 8; i++)
#pragma unroll
            for (int c = 0; c < 4; c++) oacc[mi][i][c] = 0.0f;
    float mx[2][2] = { {-INFINITY, -INFINITY}, {-INFINITY, -INFINITY} };
    float ls[2][2] = { {0.0f, 0.0f}, {0.0f, 0.0f} };

    const int ktmax = 2 * qt + 1;
    for (int kt = 0; kt <= ktmax; kt++) {
        cp_wait0();
        __syncthreads();
        if (kt < ktmax) { prefetch(kt + 1); cp_commit(); }

        const int k0 = kt * 64;
        const bool act0 = (k0 <= trow0 + 15);
        if (k0 > trow1 + 15) continue;     // warp-uniform; barrier is at loop top
        const __half* Ks = smf + (kt & 1) * 4096;
        const __half* Vs = smf + 8192 + (kt & 1) * 4096;

        // ---- S = Q K^T ----
        float sacc[2][8][4];
#pragma unroll
        for (int mi = 0; mi < 2; mi++)
#pragma unroll
            for (int i = 0; i < 8; i++)
#pragma unroll
                for (int c = 0; c < 4; c++) sacc[mi][i][c] = 0.0f;

#pragma unroll
        for (int nt = 0; nt < 8; nt++) {
            const __half* rb = Ks + (8 * nt + g) * 64;
            uint4 kb0 = *(const uint4*)(rb + ((t ^ xorsw)) * 8);
            uint4 kb1 = *(const uint4*)(rb + (((4 + t) ^ xorsw)) * 8);
#pragma unroll
            for (int mi = 0; mi < 2; mi++) {
                if (mi == 0 && !act0) continue;
                mma_f16(sacc[mi][nt], qf[mi][0][0], qf[mi][0][1], qf[mi][0][2],
                        qf[mi][0][3], kb0.x, kb0.y);
                mma_f16(sacc[mi][nt], qf[mi][1][0], qf[mi][1][1], qf[mi][1][2],
                        qf[mi][1][3], kb0.z, kb0.w);
                mma_f16(sacc[mi][nt], qf[mi][2][0], qf[mi][2][1], qf[mi][2][2],
                        qf[mi][2][3], kb1.x, kb1.y);
                mma_f16(sacc[mi][nt], qf[mi][3][0], qf[mi][3][1], qf[mi][3][2],
                        qf[mi][3][3], kb1.z, kb1.w);
            }
        }

        // ---- causal mask + online softmax + register P pack ----
        uint32_t pf[2][4][4];
#pragma unroll
        for (int mi = 0; mi < 2; mi++) {
            if (mi == 0 && !act0) continue;
            int tr = mi ? trow1 : trow0;
            if (k0 + 63 > tr) {
                int r0 = tr + g, r1 = r0 + 8;
#pragma unroll
                for (int nt = 0; nt < 8; nt++) {
                    int c0 = k0 + 8 * nt + 2 * t;
                    if (c0     > r0) sacc[mi][nt][0] = -INFINITY;
                    if (c0 + 1 > r0) sacc[mi][nt][1] = -INFINITY;
                    if (c0     > r1) sacc[mi][nt][2] = -INFINITY;
                    if (c0 + 1 > r1) sacc[mi][nt][3] = -INFINITY;
                }
            }
            float t0 = -INFINITY, t1 = -INFINITY;
#pragma unroll
            for (int nt = 0; nt < 8; nt++) {
                t0 = fmaxf(t0, fmaxf(sacc[mi][nt][0], sacc[mi][nt][1]));
                t1 = fmaxf(t1, fmaxf(sacc[mi][nt][2], sacc[mi][nt][3]));
            }
            t0 = fmaxf(t0, __shfl_xor_sync(0xffffffffu, t0, 1));
            t0 = fmaxf(t0, __shfl_xor_sync(0xffffffffu, t0, 2));
            t1 = fmaxf(t1, __shfl_xor_sync(0xffffffffu, t1, 1));
            t1 = fmaxf(t1, __shfl_xor_sync(0xffffffffu, t1, 2));
            float nm0 = fmaxf(mx[mi][0], t0), nm1 = fmaxf(mx[mi][1], t1);
            float corr0 = __expf(mx[mi][0] - nm0), corr1 = __expf(mx[mi][1] - nm1);

            float ps0 = 0.0f, ps1 = 0.0f;
#pragma unroll
            for (int nt = 0; nt < 8; nt++) {
                float p0 = __expf(sacc[mi][nt][0] - nm0);
                float p1 = __expf(sacc[mi][nt][1] - nm0);
                float p2 = __expf(sacc[mi][nt][2] - nm1);
                float p3 = __expf(sacc[mi][nt][3] - nm1);
                ps0 += p0 + p1; ps1 += p2 + p3;
                sacc[mi][nt][0] = p0; sacc[mi][nt][1] = p1;
                sacc[mi][nt][2] = p2; sacc[mi][nt][3] = p3;
            }
            ps0 += __shfl_xor_sync(0xffffffffu, ps0, 1);
            ps0 += __shfl_xor_sync(0xffffffffu, ps0, 2);
            ps1 += __shfl_xor_sync(0xffffffffu, ps1, 1);
            ps1 += __shfl_xor_sync(0xffffffffu, ps1, 2);
            ls[mi][0] = ls[mi][0] * corr0 + ps0;
            ls[mi][1] = ls[mi][1] * corr1 + ps1;
            mx[mi][0] = nm0; mx[mi][1] = nm1;
#pragma unroll
            for (int nt = 0; nt < 8; nt++) {
                oacc[mi][nt][0] *= corr0; oacc[mi][nt][1] *= corr0;
                oacc[mi][nt][2] *= corr1; oacc[mi][nt][3] *= corr1;
            }
            // pack P: QK D-frag lanes == PV A-frag lanes
#pragma unroll
            for (int s = 0; s < 4; s++) {
                pf[mi][s][0] = h2u(sacc[mi][2*s][0],   sacc[mi][2*s][1]);
                pf[mi][s][1] = h2u(sacc[mi][2*s][2],   sacc[mi][2*s][3]);
                pf[mi][s][2] = h2u(sacc[mi][2*s+1][0], sacc[mi][2*s+1][1]);
                pf[mi][s][3] = h2u(sacc[mi][2*s+1][2], sacc[mi][2*s+1][3]);
            }
        }

        // ---- O += P V ----
#pragma unroll
        for (int nt = 0; nt < 8; nt++) {
            const __half* rb = Vs + (8 * nt + g) * 64;
            uint4 vb0 = *(const uint4*)(rb + ((t ^ xorsw)) * 8);
            uint4 vb1 = *(const uint4*)(rb + (((4 + t) ^ xorsw)) * 8);
#pragma unroll
            for (int mi = 0; mi < 2; mi++) {
                if (mi == 0 && !act0) continue;
                mma_f16(oacc[mi][nt], pf[mi][0][0], pf[mi][0][1], pf[mi][0][2],
                        pf[mi][0][3], vb0.x, vb0.y);
                mma_f16(oacc[mi][nt], pf[mi][1][0], pf[mi][1][1], pf[mi][1][2],
                        pf[mi][1][3], vb0.z, vb0.w);
                mma_f16(oacc[mi][nt], pf[mi][2][0], pf[mi][2][1], pf[mi][2][2],
                        pf[mi][2][3], vb1.x, vb1.y);
                mma_f16(oacc[mi][nt], pf[mi][3][0], pf[mi][3][1], pf[mi][3][2],
                        pf[mi][3][3], vb1.z, vb1.w);
            }
        }
    }

    // ---- epilogue: fp16 k'-interleaved g_AO ----
    int b = bh >> 4, h = bh & 15;
#pragma unroll
    for (int mi = 0; mi < 2; mi++) {
        float inv0 = 1.0f / ls[mi][0], inv1 = 1.0f / ls[mi][1];
        int row0 = (mi ? trow1 : trow0) + g;
        __half* O0 = g_AO + ((size_t)(b * NS + row0)) * ND + h * HDIM;
        __half* O1 = g_AO + ((size_t)(b * NS + row0 + 8)) * ND + h * HDIM;
#pragma unroll
        for (int nt = 0; nt < 8; nt++) {
            int p = kpos(8 * nt + 2 * t);
            *(__half2*)&O0[p] = __halves2half2(
                __float2half_rn(oacc[mi][nt][0] * inv0),
                __float2half_rn(oacc[mi][nt][1] * inv0));
            *(__half2*)&O1[p] = __halves2half2(
                __float2half_rn(oacc[mi][nt][2] * inv1),
                __float2half_rn(oacc[mi][nt][3] * inv1));
        }
    }
}

// ---------------------------------------------------------------------------
extern "C" void kernel_launch(void* const* d_in, const int* in_sizes, int n_in,
                              void* d_out, int out_size)
{
    const float* x    = (const float*)d_in[0];
    const float* wq_w = (const float*)d_in[1];
    const float* wq_b = (const float*)d_in[2];
    const float* wk_w = (const float*)d_in[3];
    const float* wk_b = (const float*)d_in[4];
    const float* wv_w = (const float*)d_in[5];
    const float* wv_b = (const float*)d_in[6];
    const float* wo_w = (const float*)d_in[7];
    const float* wo_b = (const float*)d_in[8];
    float* out = (float*)d_out;

    cudaFuncSetAttribute(gemm_f16, cudaFuncAttributeMaxDynamicSharedMemorySize,
                         GEMM_SMEM);
    cudaFuncSetAttribute(flash_attn_f16,
                         cudaFuncAttributeMaxDynamicSharedMemorySize, FLASH_SMEM);

    // 8192*128 + 4*1024*128 chunks = 1,572,864 -> 6144 blocks of 256
    prep<<<6144, 256>>>(x, wq_w, wk_w, wv_w, wo_w);

    gemm_f16<<<dim3(24, NM / 128), 128, GEMM_SMEM>>>(
        wq_b, wk_b, wv_b, nullptr, 0, 1, 0);

    flash_attn_f16<<<dim3(NS / 128, NB * NH), 128, FLASH_SMEM>>>();

    gemm_f16<<<dim3(8, NM / 128), 128, GEMM_SMEM>>>(
        wo_b, nullptr, nullptr, out, 1, 0, 0);
}

// round 11
// speedup vs baseline: 2.2745x; 1.1307x over previous
#include <cuda_runtime.h>
#include <cuda_fp16.h>
#include <math.h>
#include <stdint.h>

#define NB 4
#define NS 2048
#define ND 1024
#define NH 16
#define HDIM 64
#define NM (NB*NS)
#define MM (ND*ND)

// fp16 scratch (~58 MB), all k'-interleaved per 32-block:
//   k = 16u+8v+2t+w  ->  k' = 8t+4u+2v+w
// g_XP/g_WP/g_AO: [row][1024]
// g_Q: [bh][s][64]  (pre-scaled by 0.125, d interleaved)
// g_K: [bh][key][64] (d interleaved)
// g_V: [bh][d][2048] (key interleaved)
__device__ __align__(256) __half g_Q [(size_t)NB*NH*NS*HDIM];
__device__ __align__(256) __half g_K [(size_t)NB*NH*NS*HDIM];
__device__ __align__(256) __half g_V [(size_t)NB*NH*NS*HDIM];
__device__ __align__(256) __half g_AO[(size_t)NM*ND];
__device__ __align__(256) __half g_XP[(size_t)NM*ND];
__device__ __align__(256) __half g_WP[(size_t)4*MM];

__device__ __forceinline__ void mma_f16(float d[4], uint32_t a0, uint32_t a1,
                                        uint32_t a2, uint32_t a3,
                                        uint32_t b0, uint32_t b1) {
    asm volatile(
        "mma.sync.aligned.m16n8k16.row.col.f32.f16.f16.f32 "
        "{%0,%1,%2,%3},{%4,%5,%6,%7},{%8,%9},{%0,%1,%2,%3};"
        : "+f"(d[0]), "+f"(d[1]), "+f"(d[2]), "+f"(d[3])
        : "r"(a0), "r"(a1), "r"(a2), "r"(a3), "r"(b0), "r"(b1));
}
__device__ __forceinline__ uint32_t h2u(float a, float b) {
    __half2 h = __halves2half2(__float2half_rn(a), __float2half_rn(b));
    return *(uint32_t*)&h;
}
__device__ __forceinline__ int kpos(int k) {
    return (k & ~31) | (8*((k>>1)&3) + 4*((k>>4)&1) + 2*((k>>3)&1) + (k&1));
}
__device__ __forceinline__ void cp16(void* dst, const void* src) {
    uint32_t d = (uint32_t)__cvta_generic_to_shared(dst);
    asm volatile("cp.async.cg.shared.global [%0], [%1], 16;" :: "r"(d), "l"(src));
}
__device__ __forceinline__ void cp_commit() {
    asm volatile("cp.async.commit_group;" ::: "memory");
}
__device__ __forceinline__ void cp_wait0() {
    asm volatile("cp.async.wait_group 0;" ::: "memory");
}
__device__ __forceinline__ void cp_wait1() {
    asm volatile("cp.async.wait_group 1;" ::: "memory");
}

// ---------------------------------------------------------------------------
// Prep: fp16-round x and 4 weights into k'-interleaved layout.
// ---------------------------------------------------------------------------
__global__ __launch_bounds__(256) void prep(
    const float* __restrict__ x,
    const float* __restrict__ wq, const float* __restrict__ wk,
    const float* __restrict__ wv, const float* __restrict__ wo)
{
    const size_t XC = (size_t)NM * 128;
    const size_t WC = (size_t)ND * 128;
    size_t i = (size_t)blockIdx.x * 256 + threadIdx.x;
    const float* src; __half* dst; size_t o;
    if (i < XC) { src = x; dst = g_XP; o = i; }
    else if (i < XC + 4 * WC) {
        size_t j = i - XC;
        int w = (int)(j / WC);
        o = j - (size_t)w * WC;
        src = (w == 0) ? wq : (w == 1) ? wk : (w == 2) ? wv : wo;
        dst = g_WP + (size_t)w * MM;
    } else return;
    size_t row = o >> 7;
    int c = (int)(o & 127), blk = c >> 2, t = c & 3;
    const float* s = src + row * ND + blk * 32 + 2 * t;
    uint4 v;
    v.x = h2u(s[0],  s[1]);
    v.y = h2u(s[8],  s[9]);
    v.z = h2u(s[16], s[17]);
    v.w = h2u(s[24], s[25]);
    *(uint4*)(dst + row * ND + blk * 32 + t * 8) = v;
}

// ---------------------------------------------------------------------------
// C = A @ W^T + bias, fp16 m16n8k16.  CTA 128x128x64, 4 warps (2m x 2n),
// warp 64x64, 3-stage cp.async ring (BK=64 as two 32-wide sub-blocks).
// mma issued as two passes (even k16 / odd k16) -> 32 independent mmas
// between dependent accumulator reuses.
// ---------------------------------------------------------------------------
#define STG_H 16384                 // halves per stage (A 8192 + B 8192)
#define GEMM_SMEM (3*STG_H*2)       // 98304 B

__global__ __launch_bounds__(128, 2) void gemm_f16(
    const float* __restrict__ bq, const float* __restrict__ bk,
    const float* __restrict__ bv, float* __restrict__ Cout,
    int amode, int fused, int cmode0)
{
    extern __shared__ __half smh[];
    const __half* A = amode ? g_AO : g_XP;
    int sel, nblk, cmode;
    const float* bias;
    if (fused) {
        sel  = blockIdx.x >> 3;
        nblk = blockIdx.x & 7;
        bias = (sel == 0) ? bq : (sel == 1) ? bk : bv;
        cmode = sel + 1;
    } else { sel = 3; nblk = blockIdx.x; bias = bq; cmode = cmode0; }
    const __half* W = g_WP + (size_t)sel * MM;

    const int tid = threadIdx.x, lane = tid & 31, wid = tid >> 5;
    const int wm = wid & 1, wn = wid >> 1;
    const int m0 = blockIdx.y * 128, n0 = nblk * 128;
    const int g = lane >> 2, t = lane & 3;

    float acc[4][8][4];
#pragma unroll
    for (int i = 0; i < 4; i++)
#pragma unroll
        for (int j = 0; j < 8; j++)
#pragma unroll
            for (int c = 0; c < 4; c++) acc[i][j][c] = 0.0f;

    const __half* Ap = A + (size_t)m0 * ND;
    const __half* Wp = W + (size_t)n0 * ND;

    // stage layout: A sub0 [128][32], A sub1, B sub0, B sub1 (4096 halves each)
    auto loadStage = [&](int c) {
        __half* As = smh + (c % 3) * STG_H;
        __half* Bs = As + 8192;
#pragma unroll
        for (int i = 0; i < 8; i++) {
            int f = tid + i * 128;           // 0..1023
            int row = f >> 3, q = f & 7;
            int sub = q >> 2, qq = q & 3;
            cp16(As + sub * 4096 + row * 32 + qq * 8,
                 Ap + (size_t)row * ND + c * 64 + sub * 32 + qq * 8);
            cp16(Bs + sub * 4096 + row * 32 + qq * 8,
                 Wp + (size_t)row * ND + c * 64 + sub * 32 + qq * 8);
        }
    };

    loadStage(0); cp_commit();
    loadStage(1); cp_commit();

    for (int c = 0; c < 16; c++) {
        if (c + 1 < 16) cp_wait1(); else cp_wait0();
        __syncthreads();
        if (c + 2 < 16) { loadStage(c + 2); cp_commit(); }

#pragma unroll
        for (int b = 0; b < 2; b++) {
            const __half* As = smh + (c % 3) * STG_H + b * 4096;
            const __half* Bs = As + 8192;

            uint4 alo[4], ahi[4];
#pragma unroll
            for (int mi = 0; mi < 4; mi++) {
                int r = wm * 64 + mi * 16 + g;
                alo[mi] = *(const uint4*)(As + r * 32 + t * 8);
                ahi[mi] = *(const uint4*)(As + (r + 8) * 32 + t * 8);
            }
            uint4 bv4[8];
#pragma unroll
            for (int ni = 0; ni < 8; ni++)
                bv4[ni] = *(const uint4*)(Bs + (wn * 64 + ni * 8 + g) * 32 + t * 8);

            // pass 1: even k16 step — 32 independent mmas
#pragma unroll
            for (int mi = 0; mi < 4; mi++)
#pragma unroll
                for (int ni = 0; ni < 8; ni++)
                    mma_f16(acc[mi][ni], alo[mi].x, ahi[mi].x, alo[mi].y,
                            ahi[mi].y, bv4[ni].x, bv4[ni].y);
            // pass 2: odd k16 step
#pragma unroll
            for (int mi = 0; mi < 4; mi++)
#pragma unroll
                for (int ni = 0; ni < 8; ni++)
                    mma_f16(acc[mi][ni], alo[mi].z, ahi[mi].z, alo[mi].w,
                            ahi[mi].w, bv4[ni].z, bv4[ni].w);
        }
    }

    // ---- epilogue ----
#pragma unroll
    for (int mi = 0; mi < 4; mi++) {
#pragma unroll
        for (int ni = 0; ni < 8; ni++) {
            int mlo = m0 + wm * 64 + mi * 16 + g;
            int n = n0 + wn * 64 + ni * 8 + 2 * t;
            float2 bl = *(const float2*)&bias[n];
            float cc[4] = { acc[mi][ni][0] + bl.x, acc[mi][ni][1] + bl.y,
                            acc[mi][ni][2] + bl.x, acc[mi][ni][3] + bl.y };
            if (cmode == 0) {
                *(float2*)&Cout[(size_t)mlo * ND + n] = make_float2(cc[0], cc[1]);
                *(float2*)&Cout[(size_t)(mlo + 8) * ND + n] = make_float2(cc[2], cc[3]);
            } else {
                int h = n >> 6, hd = n & 63;
#pragma unroll
                for (int rr = 0; rr < 2; rr++) {
                    int m = mlo + 8 * rr;
                    int bb = m >> 11, ss = m & 2047;
                    int bhh = bb * NH + h;
                    float ca = cc[2 * rr], cb = cc[2 * rr + 1];
                    if (cmode == 1) {
                        __half2 hv = __halves2half2(__float2half_rn(ca * 0.125f),
                                                    __float2half_rn(cb * 0.125f));
                        *(__half2*)&g_Q[((size_t)bhh * NS + ss) * HDIM + kpos(hd)] = hv;
                    } else if (cmode == 2) {
                        __half2 hv = __halves2half2(__float2half_rn(ca),
                                                    __float2half_rn(cb));
                        *(__half2*)&g_K[((size_t)bhh * NS + ss) * HDIM + kpos(hd)] = hv;
                    } else {
                        int p = kpos(ss);
                        g_V[((size_t)bhh * HDIM + hd) * NS + p] = __float2half_rn(ca);
                        g_V[((size_t)bhh * HDIM + hd + 1) * NS + p] = __float2half_rn(cb);
                    }
                }
            }
        }
    }
}

// ---------------------------------------------------------------------------
// fp16 flash attention, causal. CTA: 128 q-rows of one (b,h); 4 warps, warp
// owns m16 tiles {wq, 7-wq}. K-tiles of 64, double-buffered cp.async.
// Q frags from global; P register-resident. mma loops k-step-outer so
// dependent accumulator reuses are 8 mmas apart.
// ---------------------------------------------------------------------------
#define FLASH_SMEM 32768

__global__ __launch_bounds__(128, 2) void flash_attn_f16()
{
    extern __shared__ __half smf[];
    const int tid = threadIdx.x, lane = tid & 31, wq = tid >> 5;
    const int g = lane >> 2, t = lane & 3;
    const int bh = blockIdx.y;
    const int qt = (int)gridDim.x - 1 - (int)blockIdx.x;
    const int q0 = qt * 128;
    const int trow0 = q0 + wq * 16, trow1 = q0 + (7 - wq) * 16;
    const int xorsw = (g & 1) << 2;

    const __half* Kb = g_K + (size_t)bh * NS * HDIM;
    const __half* Vb = g_V + (size_t)bh * HDIM * NS;

    // ---- Q fragments (direct from global; 8 LDG.128) ----
    uint32_t qf[2][4][4];
    {
        const int rows[2] = { trow0, trow1 };
#pragma unroll
        for (int mi = 0; mi < 2; mi++) {
            const __half* p0 = g_Q + ((size_t)bh * NS + rows[mi] + g) * HDIM;
            const __half* p1 = g_Q + ((size_t)bh * NS + rows[mi] + g + 8) * HDIM;
            uint4 a0 = *(const uint4*)(p0 + t * 8);
            uint4 a1 = *(const uint4*)(p1 + t * 8);
            uint4 b0 = *(const uint4*)(p0 + 32 + t * 8);
            uint4 b1 = *(const uint4*)(p1 + 32 + t * 8);
            qf[mi][0][0]=a0.x; qf[mi][0][1]=a1.x; qf[mi][0][2]=a0.y; qf[mi][0][3]=a1.y;
            qf[mi][1][0]=a0.z; qf[mi][1][1]=a1.z; qf[mi][1][2]=a0.w; qf[mi][1][3]=a1.w;
            qf[mi][2][0]=b0.x; qf[mi][2][1]=b1.x; qf[mi][2][2]=b0.y; qf[mi][2][3]=b1.y;
            qf[mi][3][0]=b0.z; qf[mi][3][1]=b1.z; qf[mi][3][2]=b0.w; qf[mi][3][3]=b1.w;
        }
    }

    auto prefetch = [&](int kt) {
        __half* Ks = smf + (kt & 1) * 4096;
        __half* Vs = smf + 8192 + (kt & 1) * 4096;
        int kk0 = kt * 64;
#pragma unroll
        for (int i = 0; i < 4; i++) {
            int cid = tid + i * 128;
            int row = cid >> 3, c = cid & 7;
            int sw = c ^ ((row & 1) << 2);
            cp16(Ks + row * 64 + sw * 8, Kb + (size_t)(kk0 + row) * HDIM + c * 8);
            cp16(Vs + row * 64 + sw * 8, Vb + (size_t)row * NS + kk0 + c * 8);
        }
    };

    prefetch(0); cp_commit();

    float oacc[2][8][4];
#pragma unroll
    for (int mi = 0; mi < 2; mi++)
#pragma unroll
        for (int i = 0; i < 8; i++)
#pragma unroll
            for (int c = 0; c < 4; c++) oacc[mi][i][c] = 0.0f;
    float mx[2][2] = { {-INFINITY, -INFINITY}, {-INFINITY, -INFINITY} };
    float ls[2][2] = { {0.0f, 0.0f}, {0.0f, 0.0f} };

    const int ktmax = 2 * qt + 1;
    for (int kt = 0; kt <= ktmax; kt++) {
        cp_wait0();
        __syncthreads();
        if (kt < ktmax) { prefetch(kt + 1); cp_commit(); }

        const int k0 = kt * 64;
        const bool act0 = (k0 <= trow0 + 15);
        if (k0 > trow1 + 15) continue;     // warp-uniform
        const __half* Ks = smf + (kt & 1) * 4096;
        const __half* Vs = smf + 8192 + (kt & 1) * 4096;

        // ---- S = Q K^T (k-step outer: 8-mma gap between dependents) ----
        float sacc[2][8][4];
#pragma unroll
        for (int mi = 0; mi < 2; mi++)
#pragma unroll
            for (int i = 0; i < 8; i++)
#pragma unroll
                for (int c = 0; c < 4; c++) sacc[mi][i][c] = 0.0f;

#pragma unroll
        for (int nth = 0; nth < 2; nth++) {
            uint4 kb[4][2];
#pragma unroll
            for (int j = 0; j < 4; j++) {
                const __half* rb = Ks + (8 * (nth * 4 + j) + g) * 64;
                kb[j][0] = *(const uint4*)(rb + (t ^ xorsw) * 8);
                kb[j][1] = *(const uint4*)(rb + ((4 + t) ^ xorsw) * 8);
            }
#pragma unroll
            for (int s = 0; s < 4; s++) {
#pragma unroll
                for (int j = 0; j < 4; j++) {
                    int nt = nth * 4 + j;
                    uint32_t b0 = (s & 1) ? kb[j][s >> 1].z : kb[j][s >> 1].x;
                    uint32_t b1 = (s & 1) ? kb[j][s >> 1].w : kb[j][s >> 1].y;
#pragma unroll
                    for (int mi = 0; mi < 2; mi++) {
                        if (mi == 0 && !act0) continue;
                        mma_f16(sacc[mi][nt], qf[mi][s][0], qf[mi][s][1],
                                qf[mi][s][2], qf[mi][s][3], b0, b1);
                    }
                }
            }
        }

        // ---- causal mask + online softmax + register P pack ----
        uint32_t pf[2][4][4];
#pragma unroll
        for (int mi = 0; mi < 2; mi++) {
            if (mi == 0 && !act0) continue;
            int tr = mi ? trow1 : trow0;
            if (k0 + 63 > tr) {
                int r0 = tr + g, r1 = r0 + 8;
#pragma unroll
                for (int nt = 0; nt < 8; nt++) {
                    int c0 = k0 + 8 * nt + 2 * t;
                    if (c0     > r0) sacc[mi][nt][0] = -INFINITY;
                    if (c0 + 1 > r0) sacc[mi][nt][1] = -INFINITY;
                    if (c0     > r1) sacc[mi][nt][2] = -INFINITY;
                    if (c0 + 1 > r1) sacc[mi][nt][3] = -INFINITY;
                }
            }
            float t0 = -INFINITY, t1 = -INFINITY;
#pragma unroll
            for (int nt = 0; nt < 8; nt++) {
                t0 = fmaxf(t0, fmaxf(sacc[mi][nt][0], sacc[mi][nt][1]));
                t1 = fmaxf(t1, fmaxf(sacc[mi][nt][2], sacc[mi][nt][3]));
            }
            t0 = fmaxf(t0, __shfl_xor_sync(0xffffffffu, t0, 1));
            t0 = fmaxf(t0, __shfl_xor_sync(0xffffffffu, t0, 2));
            t1 = fmaxf(t1, __shfl_xor_sync(0xffffffffu, t1, 1));
            t1 = fmaxf(t1, __shfl_xor_sync(0xffffffffu, t1, 2));
            float nm0 = fmaxf(mx[mi][0], t0), nm1 = fmaxf(mx[mi][1], t1);
            float corr0 = __expf(mx[mi][0] - nm0), corr1 = __expf(mx[mi][1] - nm1);

            float ps0 = 0.0f, ps1 = 0.0f;
#pragma unroll
            for (int nt = 0; nt < 8; nt++) {
                float p0 = __expf(sacc[mi][nt][0] - nm0);
                float p1 = __expf(sacc[mi][nt][1] - nm0);
                float p2 = __expf(sacc[mi][nt][2] - nm1);
                float p3 = __expf(sacc[mi][nt][3] - nm1);
                ps0 += p0 + p1; ps1 += p2 + p3;
                sacc[mi][nt][0] = p0; sacc[mi][nt][1] = p1;
                sacc[mi][nt][2] = p2; sacc[mi][nt][3] = p3;
            }
            ps0 += __shfl_xor_sync(0xffffffffu, ps0, 1);
            ps0 += __shfl_xor_sync(0xffffffffu, ps0, 2);
            ps1 += __shfl_xor_sync(0xffffffffu, ps1, 1);
            ps1 += __shfl_xor_sync(0xffffffffu, ps1, 2);
            ls[mi][0] = ls[mi][0] * corr0 + ps0;
            ls[mi][1] = ls[mi][1] * corr1 + ps1;
            mx[mi][0] = nm0; mx[mi][1] = nm1;
#pragma unroll
            for (int nt = 0; nt < 8; nt++) {
                oacc[mi][nt][0] *= corr0; oacc[mi][nt][1] *= corr0;
                oacc[mi][nt][2] *= corr1; oacc[mi][nt][3] *= corr1;
            }
#pragma unroll
            for (int s = 0; s < 4; s++) {
                pf[mi][s][0] = h2u(sacc[mi][2*s][0],   sacc[mi][2*s][1]);
                pf[mi][s][1] = h2u(sacc[mi][2*s][2],   sacc[mi][2*s][3]);
                pf[mi][s][2] = h2u(sacc[mi][2*s+1][0], sacc[mi][2*s+1][1]);
                pf[mi][s][3] = h2u(sacc[mi][2*s+1][2], sacc[mi][2*s+1][3]);
            }
        }

        // ---- O += P V (k-step outer) ----
#pragma unroll
        for (int nth = 0; nth < 2; nth++) {
            uint4 vb[4][2];
#pragma unroll
            for (int j = 0; j < 4; j++) {
                const __half* rb = Vs + (8 * (nth * 4 + j) + g) * 64;
                vb[j][0] = *(const uint4*)(rb + (t ^ xorsw) * 8);
                vb[j][1] = *(const uint4*)(rb + ((4 + t) ^ xorsw) * 8);
            }
#pragma unroll
            for (int s = 0; s < 4; s++) {
#pragma unroll
                for (int j = 0; j < 4; j++) {
                    int nt = nth * 4 + j;
                    uint32_t b0 = (s & 1) ? vb[j][s >> 1].z : vb[j][s >> 1].x;
                    uint32_t b1 = (s & 1) ? vb[j][s >> 1].w : vb[j][s >> 1].y;
#pragma unroll
                    for (int mi = 0; mi < 2; mi++) {
                        if (mi == 0 && !act0) continue;
                        mma_f16(oacc[mi][nt], pf[mi][s][0], pf[mi][s][1],
                                pf[mi][s][2], pf[mi][s][3], b0, b1);
                    }
                }
            }
        }
    }

    // ---- epilogue: fp16 k'-interleaved g_AO ----
    int b = bh >> 4, h = bh & 15;
#pragma unroll
    for (int mi = 0; mi < 2; mi++) {
        float inv0 = 1.0f / ls[mi][0], inv1 = 1.0f / ls[mi][1];
        int row0 = (mi ? trow1 : trow0) + g;
        __half* O0 = g_AO + ((size_t)(b * NS + row0)) * ND + h * HDIM;
        __half* O1 = g_AO + ((size_t)(b * NS + row0 + 8)) * ND + h * HDIM;
#pragma unroll
        for (int nt = 0; nt < 8; nt++) {
            int p = kpos(8 * nt + 2 * t);
            *(__half2*)&O0[p] = __halves2half2(
                __float2half_rn(oacc[mi][nt][0] * inv0),
                __float2half_rn(oacc[mi][nt][1] * inv0));
            *(__half2*)&O1[p] = __halves2half2(
                __float2half_rn(oacc[mi][nt][2] * inv1),
                __float2half_rn(oacc[mi][nt][3] * inv1));
        }
    }
}

// ---------------------------------------------------------------------------
extern "C" void kernel_launch(void* const* d_in, const int* in_sizes, int n_in,
                              void* d_out, int out_size)
{
    const float* x    = (const float*)d_in[0];
    const float* wq_w = (const float*)d_in[1];
    const float* wq_b = (const float*)d_in[2];
    const float* wk_w = (const float*)d_in[3];
    const float* wk_b = (const float*)d_in[4];
    const float* wv_w = (const float*)d_in[5];
    const float* wv_b = (const float*)d_in[6];
    const float* wo_w = (const float*)d_in[7];
    const float* wo_b = (const float*)d_in[8];
    float* out = (float*)d_out;

    cudaFuncSetAttribute(gemm_f16, cudaFuncAttributeMaxDynamicSharedMemorySize,
                         GEMM_SMEM);
    cudaFuncSetAttribute(flash_attn_f16,
                         cudaFuncAttributeMaxDynamicSharedMemorySize, FLASH_SMEM);

    prep<<<6144, 256>>>(x, wq_w, wk_w, wv_w, wo_w);

    gemm_f16<<<dim3(24, NM / 128), 128, GEMM_SMEM>>>(
        wq_b, wk_b, wv_b, nullptr, 0, 1, 0);

    flash_attn_f16<<<dim3(NS / 128, NB * NH), 128, FLASH_SMEM>>>();

    gemm_f16<<<dim3(8, NM / 128), 128, GEMM_SMEM>>>(
        wo_b, nullptr, nullptr, out, 1, 0, 0);
}

// round 12
// speedup vs baseline: 2.3122x; 1.0166x over previous
#include <cuda_runtime.h>
#include <cuda_fp16.h>
#include <math.h>
#include <stdint.h>

#define NB 4
#define NS 2048
#define ND 1024
#define NH 16
#define HDIM 64
#define NM (NB*NS)
#define MM (ND*ND)

// fp16 scratch (~58 MB), all k'-interleaved per 32-block:
//   k = 16u+8v+2t+w  ->  k' = 8t+4u+2v+w
// g_XP/g_WP/g_AO: [row][1024]
// g_Q: [bh][s][64]  (pre-scaled by 0.125, d interleaved)
// g_K: [bh][key][64] (d interleaved)
// g_V: [bh][d][2048] (key interleaved)
__device__ __align__(256) __half g_Q [(size_t)NB*NH*NS*HDIM];
__device__ __align__(256) __half g_K [(size_t)NB*NH*NS*HDIM];
__device__ __align__(256) __half g_V [(size_t)NB*NH*NS*HDIM];
__device__ __align__(256) __half g_AO[(size_t)NM*ND];
__device__ __align__(256) __half g_XP[(size_t)NM*ND];
__device__ __align__(256) __half g_WP[(size_t)4*MM];

__device__ __forceinline__ void mma_f16(float d[4], uint32_t a0, uint32_t a1,
                                        uint32_t a2, uint32_t a3,
                                        uint32_t b0, uint32_t b1) {
    asm volatile(
        "mma.sync.aligned.m16n8k16.row.col.f32.f16.f16.f32 "
        "{%0,%1,%2,%3},{%4,%5,%6,%7},{%8,%9},{%0,%1,%2,%3};"
        : "+f"(d[0]), "+f"(d[1]), "+f"(d[2]), "+f"(d[3])
        : "r"(a0), "r"(a1), "r"(a2), "r"(a3), "r"(b0), "r"(b1));
}
__device__ __forceinline__ uint32_t h2u(float a, float b) {
    __half2 h = __halves2half2(__float2half_rn(a), __float2half_rn(b));
    return *(uint32_t*)&h;
}
__device__ __forceinline__ int kpos(int k) {
    return (k & ~31) | (8*((k>>1)&3) + 4*((k>>4)&1) + 2*((k>>3)&1) + (k&1));
}
__device__ __forceinline__ void cp16(void* dst, const void* src) {
    uint32_t d = (uint32_t)__cvta_generic_to_shared(dst);
    asm volatile("cp.async.cg.shared.global [%0], [%1], 16;" :: "r"(d), "l"(src));
}
__device__ __forceinline__ void cp_commit() {
    asm volatile("cp.async.commit_group;" ::: "memory");
}
__device__ __forceinline__ void cp_wait0() {
    asm volatile("cp.async.wait_group 0;" ::: "memory");
}
__device__ __forceinline__ void cp_wait1() {
    asm volatile("cp.async.wait_group 1;" ::: "memory");
}

// ---------------------------------------------------------------------------
// Prep: fp16-round x and 4 weights into k'-interleaved layout.
// ---------------------------------------------------------------------------
__global__ __launch_bounds__(256) void prep(
    const float* __restrict__ x,
    const float* __restrict__ wq, const float* __restrict__ wk,
    const float* __restrict__ wv, const float* __restrict__ wo)
{
    const size_t XC = (size_t)NM * 128;
    const size_t WC = (size_t)ND * 128;
    size_t i = (size_t)blockIdx.x * 256 + threadIdx.x;
    const float* src; __half* dst; size_t o;
    if (i < XC) { src = x; dst = g_XP; o = i; }
    else if (i < XC + 4 * WC) {
        size_t j = i - XC;
        int w = (int)(j / WC);
        o = j - (size_t)w * WC;
        src = (w == 0) ? wq : (w == 1) ? wk : (w == 2) ? wv : wo;
        dst = g_WP + (size_t)w * MM;
    } else return;
    size_t row = o >> 7;
    int c = (int)(o & 127), blk = c >> 2, t = c & 3;
    const float* s = src + row * ND + blk * 32 + 2 * t;
    uint4 v;
    v.x = h2u(s[0],  s[1]);
    v.y = h2u(s[8],  s[9]);
    v.z = h2u(s[16], s[17]);
    v.w = h2u(s[24], s[25]);
    *(uint4*)(dst + row * ND + blk * 32 + t * 8) = v;
}

// ---------------------------------------------------------------------------
// C = A @ W^T + bias, fp16 m16n8k16.  CTA 128x128x64, 8 warps (2m x 4n),
// warp tile 64x32, 3-stage cp.async ring.  256 thr, 2 CTAs/SM ->
// 4 warps/SMSP (tensor-pipe utilization is warp-count-bound).
// ---------------------------------------------------------------------------
#define STG_H 16384                 // halves per stage (A 8192 + B 8192)
#define GEMM_SMEM (3*STG_H*2)       // 98304 B

__global__ __launch_bounds__(256, 2) void gemm_f16(
    const float* __restrict__ bq, const float* __restrict__ bk,
    const float* __restrict__ bv, float* __restrict__ Cout,
    int amode, int fused, int cmode0)
{
    extern __shared__ __half smh[];
    const __half* A = amode ? g_AO : g_XP;
    int sel, nblk, cmode;
    const float* bias;
    if (fused) {
        sel  = blockIdx.x >> 3;
        nblk = blockIdx.x & 7;
        bias = (sel == 0) ? bq : (sel == 1) ? bk : bv;
        cmode = sel + 1;
    } else { sel = 3; nblk = blockIdx.x; bias = bq; cmode = cmode0; }
    const __half* W = g_WP + (size_t)sel * MM;

    const int tid = threadIdx.x, lane = tid & 31, wid = tid >> 5;
    const int wm = wid & 1, wn = wid >> 1;          // 2 x 4 warp grid
    const int m0 = blockIdx.y * 128, n0 = nblk * 128;
    const int g = lane >> 2, t = lane & 3;

    float acc[4][4][4];
#pragma unroll
    for (int i = 0; i < 4; i++)
#pragma unroll
        for (int j = 0; j < 4; j++)
#pragma unroll
            for (int c = 0; c < 4; c++) acc[i][j][c] = 0.0f;

    const __half* Ap = A + (size_t)m0 * ND;
    const __half* Wp = W + (size_t)n0 * ND;

    // stage layout: A sub0 [128][32], A sub1, B sub0, B sub1 (4096 halves each)
    auto loadStage = [&](int c) {
        __half* As = smh + (c % 3) * STG_H;
        __half* Bs = As + 8192;
#pragma unroll
        for (int i = 0; i < 4; i++) {
            int f = tid + i * 256;           // 0..1023
            int row = f >> 3, q = f & 7;
            int sub = q >> 2, qq = q & 3;
            cp16(As + sub * 4096 + row * 32 + qq * 8,
                 Ap + (size_t)row * ND + c * 64 + sub * 32 + qq * 8);
            cp16(Bs + sub * 4096 + row * 32 + qq * 8,
                 Wp + (size_t)row * ND + c * 64 + sub * 32 + qq * 8);
        }
    };

    loadStage(0); cp_commit();
    loadStage(1); cp_commit();

    for (int c = 0; c < 16; c++) {
        if (c + 1 < 16) cp_wait1(); else cp_wait0();
        __syncthreads();
        if (c + 2 < 16) { loadStage(c + 2); cp_commit(); }

#pragma unroll
        for (int b = 0; b < 2; b++) {
            const __half* As = smh + (c % 3) * STG_H + b * 4096;
            const __half* Bs = As + 8192;

            uint4 alo[4], ahi[4];
#pragma unroll
            for (int mi = 0; mi < 4; mi++) {
                int r = wm * 64 + mi * 16 + g;
                alo[mi] = *(const uint4*)(As + r * 32 + t * 8);
                ahi[mi] = *(const uint4*)(As + (r + 8) * 32 + t * 8);
            }
            uint4 bv4[4];
#pragma unroll
            for (int ni = 0; ni < 4; ni++)
                bv4[ni] = *(const uint4*)(Bs + (wn * 32 + ni * 8 + g) * 32 + t * 8);

            // pass 1: even k16 step — 16 independent mmas
#pragma unroll
            for (int mi = 0; mi < 4; mi++)
#pragma unroll
                for (int ni = 0; ni < 4; ni++)
                    mma_f16(acc[mi][ni], alo[mi].x, ahi[mi].x, alo[mi].y,
                            ahi[mi].y, bv4[ni].x, bv4[ni].y);
            // pass 2: odd k16 step
#pragma unroll
            for (int mi = 0; mi < 4; mi++)
#pragma unroll
                for (int ni = 0; ni < 4; ni++)
                    mma_f16(acc[mi][ni], alo[mi].z, ahi[mi].z, alo[mi].w,
                            ahi[mi].w, bv4[ni].z, bv4[ni].w);
        }
    }

    // ---- epilogue ----
#pragma unroll
    for (int mi = 0; mi < 4; mi++) {
#pragma unroll
        for (int ni = 0; ni < 4; ni++) {
            int mlo = m0 + wm * 64 + mi * 16 + g;
            int n = n0 + wn * 32 + ni * 8 + 2 * t;
            float2 bl = *(const float2*)&bias[n];
            float cc[4] = { acc[mi][ni][0] + bl.x, acc[mi][ni][1] + bl.y,
                            acc[mi][ni][2] + bl.x, acc[mi][ni][3] + bl.y };
            if (cmode == 0) {
                *(float2*)&Cout[(size_t)mlo * ND + n] = make_float2(cc[0], cc[1]);
                *(float2*)&Cout[(size_t)(mlo + 8) * ND + n] = make_float2(cc[2], cc[3]);
            } else {
                int h = n >> 6, hd = n & 63;
#pragma unroll
                for (int rr = 0; rr < 2; rr++) {
                    int m = mlo + 8 * rr;
                    int bb = m >> 11, ss = m & 2047;
                    int bhh = bb * NH + h;
                    float ca = cc[2 * rr], cb = cc[2 * rr + 1];
                    if (cmode == 1) {
                        __half2 hv = __halves2half2(__float2half_rn(ca * 0.125f),
                                                    __float2half_rn(cb * 0.125f));
                        *(__half2*)&g_Q[((size_t)bhh * NS + ss) * HDIM + kpos(hd)] = hv;
                    } else if (cmode == 2) {
                        __half2 hv = __halves2half2(__float2half_rn(ca),
                                                    __float2half_rn(cb));
                        *(__half2*)&g_K[((size_t)bhh * NS + ss) * HDIM + kpos(hd)] = hv;
                    } else {
                        int p = kpos(ss);
                        g_V[((size_t)bhh * HDIM + hd) * NS + p] = __float2half_rn(ca);
                        g_V[((size_t)bhh * HDIM + hd + 1) * NS + p] = __float2half_rn(cb);
                    }
                }
            }
        }
    }
}

// ---------------------------------------------------------------------------
// fp16 flash attention, causal. CTA: 128 q-rows of one (b,h); 8 warps,
// warp owns ONE m16 tile (wq). 256 thr, 2 CTAs/SM -> 4 warps/SMSP.
// K-tiles of 64, double-buffered cp.async. Q frags from global;
// P register-resident.
// ---------------------------------------------------------------------------
#define FLASH_SMEM 32768

__global__ __launch_bounds__(256, 2) void flash_attn_f16()
{
    extern __shared__ __half smf[];
    const int tid = threadIdx.x, lane = tid & 31, wq = tid >> 5;
    const int g = lane >> 2, t = lane & 3;
    const int bh = blockIdx.y;
    const int qt = (int)gridDim.x - 1 - (int)blockIdx.x;
    const int q0 = qt * 128;
    const int trow = q0 + wq * 16;
    const int xorsw = (g & 1) << 2;

    const __half* Kb = g_K + (size_t)bh * NS * HDIM;
    const __half* Vb = g_V + (size_t)bh * HDIM * NS;

    // ---- Q fragments (direct from global; 4 LDG.128) ----
    uint32_t qf[4][4];
    {
        const __half* p0 = g_Q + ((size_t)bh * NS + trow + g) * HDIM;
        const __half* p1 = g_Q + ((size_t)bh * NS + trow + g + 8) * HDIM;
        uint4 a0 = *(const uint4*)(p0 + t * 8);
        uint4 a1 = *(const uint4*)(p1 + t * 8);
        uint4 b0 = *(const uint4*)(p0 + 32 + t * 8);
        uint4 b1 = *(const uint4*)(p1 + 32 + t * 8);
        qf[0][0]=a0.x; qf[0][1]=a1.x; qf[0][2]=a0.y; qf[0][3]=a1.y;
        qf[1][0]=a0.z; qf[1][1]=a1.z; qf[1][2]=a0.w; qf[1][3]=a1.w;
        qf[2][0]=b0.x; qf[2][1]=b1.x; qf[2][2]=b0.y; qf[2][3]=b1.y;
        qf[3][0]=b0.z; qf[3][1]=b1.z; qf[3][2]=b0.w; qf[3][3]=b1.w;
    }

    auto prefetch = [&](int kt) {
        __half* Ks = smf + (kt & 1) * 4096;
        __half* Vs = smf + 8192 + (kt & 1) * 4096;
        int kk0 = kt * 64;
#pragma unroll
        for (int i = 0; i < 2; i++) {
            int cid = tid + i * 256;       // 0..511
            int row = cid >> 3, c = cid & 7;
            int sw = c ^ ((row & 1) << 2);
            cp16(Ks + row * 64 + sw * 8, Kb + (size_t)(kk0 + row) * HDIM + c * 8);
            cp16(Vs + row * 64 + sw * 8, Vb + (size_t)row * NS + kk0 + c * 8);
        }
    };

    prefetch(0); cp_commit();

    float oacc[8][4];
#pragma unroll
    for (int i = 0; i < 8; i++)
#pragma unroll
        for (int c = 0; c < 4; c++) oacc[i][c] = 0.0f;
    float mx0 = -INFINITY, mx1 = -INFINITY;
    float ls0 = 0.0f, ls1 = 0.0f;

    const int ktmax = 2 * qt + 1;
    for (int kt = 0; kt <= ktmax; kt++) {
        cp_wait0();
        __syncthreads();
        if (kt < ktmax) { prefetch(kt + 1); cp_commit(); }

        const int k0 = kt * 64;
        if (k0 > trow + 15) continue;      // warp-uniform; barrier at loop top
        const __half* Ks = smf + (kt & 1) * 4096;
        const __half* Vs = smf + 8192 + (kt & 1) * 4096;

        // ---- S = Q K^T (k-step outer) ----
        float sacc[8][4];
#pragma unroll
        for (int i = 0; i < 8; i++)
#pragma unroll
            for (int c = 0; c < 4; c++) sacc[i][c] = 0.0f;

#pragma unroll
        for (int nth = 0; nth < 2; nth++) {
            uint4 kb[4][2];
#pragma unroll
            for (int j = 0; j < 4; j++) {
                const __half* rb = Ks + (8 * (nth * 4 + j) + g) * 64;
                kb[j][0] = *(const uint4*)(rb + (t ^ xorsw) * 8);
                kb[j][1] = *(const uint4*)(rb + ((4 + t) ^ xorsw) * 8);
            }
#pragma unroll
            for (int s = 0; s < 4; s++)
#pragma unroll
                for (int j = 0; j < 4; j++) {
                    int nt = nth * 4 + j;
                    uint32_t b0 = (s & 1) ? kb[j][s >> 1].z : kb[j][s >> 1].x;
                    uint32_t b1 = (s & 1) ? kb[j][s >> 1].w : kb[j][s >> 1].y;
                    mma_f16(sacc[nt], qf[s][0], qf[s][1], qf[s][2], qf[s][3],
                            b0, b1);
                }
        }

        // ---- causal mask + online softmax + register P pack ----
        if (k0 + 63 > trow) {
            int r0 = trow + g, r1 = r0 + 8;
#pragma unroll
            for (int nt = 0; nt < 8; nt++) {
                int c0 = k0 + 8 * nt + 2 * t;
                if (c0     > r0) sacc[nt][0] = -INFINITY;
                if (c0 + 1 > r0) sacc[nt][1] = -INFINITY;
                if (c0     > r1) sacc[nt][2] = -INFINITY;
                if (c0 + 1 > r1) sacc[nt][3] = -INFINITY;
            }
        }
        float t0 = -INFINITY, t1 = -INFINITY;
#pragma unroll
        for (int nt = 0; nt < 8; nt++) {
            t0 = fmaxf(t0, fmaxf(sacc[nt][0], sacc[nt][1]));
            t1 = fmaxf(t1, fmaxf(sacc[nt][2], sacc[nt][3]));
        }
        t0 = fmaxf(t0, __shfl_xor_sync(0xffffffffu, t0, 1));
        t0 = fmaxf(t0, __shfl_xor_sync(0xffffffffu, t0, 2));
        t1 = fmaxf(t1, __shfl_xor_sync(0xffffffffu, t1, 1));
        t1 = fmaxf(t1, __shfl_xor_sync(0xffffffffu, t1, 2));
        float nm0 = fmaxf(mx0, t0), nm1 = fmaxf(mx1, t1);
        float corr0 = __expf(mx0 - nm0), corr1 = __expf(mx1 - nm1);

        float ps0 = 0.0f, ps1 = 0.0f;
#pragma unroll
        for (int nt = 0; nt < 8; nt++) {
            float p0 = __expf(sacc[nt][0] - nm0);
            float p1 = __expf(sacc[nt][1] - nm0);
            float p2 = __expf(sacc[nt][2] - nm1);
            float p3 = __expf(sacc[nt][3] - nm1);
            ps0 += p0 + p1; ps1 += p2 + p3;
            sacc[nt][0] = p0; sacc[nt][1] = p1;
            sacc[nt][2] = p2; sacc[nt][3] = p3;
        }
        ps0 += __shfl_xor_sync(0xffffffffu, ps0, 1);
        ps0 += __shfl_xor_sync(0xffffffffu, ps0, 2);
        ps1 += __shfl_xor_sync(0xffffffffu, ps1, 1);
        ps1 += __shfl_xor_sync(0xffffffffu, ps1, 2);
        ls0 = ls0 * corr0 + ps0;
        ls1 = ls1 * corr1 + ps1;
        mx0 = nm0; mx1 = nm1;
#pragma unroll
        for (int nt = 0; nt < 8; nt++) {
            oacc[nt][0] *= corr0; oacc[nt][1] *= corr0;
            oacc[nt][2] *= corr1; oacc[nt][3] *= corr1;
        }
        uint32_t pf[4][4];
#pragma unroll
        for (int s = 0; s < 4; s++) {
            pf[s][0] = h2u(sacc[2*s][0],   sacc[2*s][1]);
            pf[s][1] = h2u(sacc[2*s][2],   sacc[2*s][3]);
            pf[s][2] = h2u(sacc[2*s+1][0], sacc[2*s+1][1]);
            pf[s][3] = h2u(sacc[2*s+1][2], sacc[2*s+1][3]);
        }

        // ---- O += P V (k-step outer) ----
#pragma unroll
        for (int nth = 0; nth < 2; nth++) {
            uint4 vb[4][2];
#pragma unroll
            for (int j = 0; j < 4; j++) {
                const __half* rb = Vs + (8 * (nth * 4 + j) + g) * 64;
                vb[j][0] = *(const uint4*)(rb + (t ^ xorsw) * 8);
                vb[j][1] = *(const uint4*)(rb + ((4 + t) ^ xorsw) * 8);
            }
#pragma unroll
            for (int s = 0; s < 4; s++)
#pragma unroll
                for (int j = 0; j < 4; j++) {
                    int nt = nth * 4 + j;
                    uint32_t b0 = (s & 1) ? vb[j][s >> 1].z : vb[j][s >> 1].x;
                    uint32_t b1 = (s & 1) ? vb[j][s >> 1].w : vb[j][s >> 1].y;
                    mma_f16(oacc[nt], pf[s][0], pf[s][1], pf[s][2], pf[s][3],
                            b0, b1);
                }
        }
    }

    // ---- epilogue: fp16 k'-interleaved g_AO ----
    int b = bh >> 4, h = bh & 15;
    float inv0 = 1.0f / ls0, inv1 = 1.0f / ls1;
    int row0 = trow + g;
    __half* O0 = g_AO + ((size_t)(b * NS + row0)) * ND + h * HDIM;
    __half* O1 = g_AO + ((size_t)(b * NS + row0 + 8)) * ND + h * HDIM;
#pragma unroll
    for (int nt = 0; nt < 8; nt++) {
        int p = kpos(8 * nt + 2 * t);
        *(__half2*)&O0[p] = __halves2half2(
            __float2half_rn(oacc[nt][0] * inv0),
            __float2half_rn(oacc[nt][1] * inv0));
        *(__half2*)&O1[p] = __halves2half2(
            __float2half_rn(oacc[nt][2] * inv1),
            __float2half_rn(oacc[nt][3] * inv1));
    }
}

// ---------------------------------------------------------------------------
extern "C" void kernel_launch(void* const* d_in, const int* in_sizes, int n_in,
                              void* d_out, int out_size)
{
    const float* x    = (const float*)d_in[0];
    const float* wq_w = (const float*)d_in[1];
    const float* wq_b = (const float*)d_in[2];
    const float* wk_w = (const float*)d_in[3];
    const float* wk_b = (const float*)d_in[4];
    const float* wv_w = (const float*)d_in[5];
    const float* wv_b = (const float*)d_in[6];
    const float* wo_w = (const float*)d_in[7];
    const float* wo_b = (const float*)d_in[8];
    float* out = (float*)d_out;

    cudaFuncSetAttribute(gemm_f16, cudaFuncAttributeMaxDynamicSharedMemorySize,
                         GEMM_SMEM);
    cudaFuncSetAttribute(flash_attn_f16,
                         cudaFuncAttributeMaxDynamicSharedMemorySize, FLASH_SMEM);

    prep<<<6144, 256>>>(x, wq_w, wk_w, wv_w, wo_w);

    gemm_f16<<<dim3(24, NM / 128), 256, GEMM_SMEM>>>(
        wq_b, wk_b, wv_b, nullptr, 0, 1, 0);

    flash_attn_f16<<<dim3(NS / 128, NB * NH), 256, FLASH_SMEM>>>();

    gemm_f16<<<dim3(8, NM / 128), 256, GEMM_SMEM>>>(
        wo_b, nullptr, nullptr, out, 1, 0, 0);
}